// round 3
// baseline (speedup 1.0000x reference)
#include <cuda_runtime.h>
#include <math.h>

#define N_NODES 50000
#define N_EDGES 800000
#define IN_DIM  128
#define HID_DIM 256
#define OUT_DIM 128

// ---------------- scratch (device globals: no allocs allowed) ----------------
__device__ int   g_is64;
__device__ int   g_src [N_EDGES];
__device__ int   g_dst [N_EDGES];
__device__ float g_dinv[N_NODES];                    // deg -> rsqrt(deg)
__device__ float g_h1s [N_NODES * HID_DIM];          // (x@W1) * dinv[row]
__device__ float g_agg1[N_NODES * HID_DIM];          // layer-1 aggregation
__device__ float g_h2s [N_NODES * OUT_DIM];          // (h@W2) * dinv[row]

// ---------------- edge index dtype detection + conversion ----------------
// If the buffer is int64 (values < 2^31, non-negative), every odd 32-bit word
// is zero. If int32, odd words are node ids (random in [0,50000)) -> ~never all 0.
__global__ void detect_kernel(const int* __restrict__ ei_raw) {
    int ornz = 0;
    #pragma unroll 8
    for (int i = 0; i < 512; i++) ornz |= ei_raw[2 * i + 1];
    g_is64 = (ornz == 0) ? 1 : 0;
}

__global__ void convert_edges_kernel(const int* __restrict__ ei_raw) {
    int e = blockIdx.x * blockDim.x + threadIdx.x;
    if (e >= N_EDGES) return;
    if (g_is64) {
        const long long* p = (const long long*)ei_raw;
        g_src[e] = (int)p[e];
        g_dst[e] = (int)p[N_EDGES + e];
    } else {
        g_src[e] = ei_raw[e];
        g_dst[e] = ei_raw[N_EDGES + e];
    }
}

// ---------------- degree / dinv ----------------
__global__ void init_deg_kernel() {
    int i = blockIdx.x * blockDim.x + threadIdx.x;
    if (i < N_NODES) g_dinv[i] = 1.0f;  // self loop
}

__global__ void count_deg_kernel() {
    int e = blockIdx.x * blockDim.x + threadIdx.x;
    if (e < N_EDGES) atomicAdd(&g_dinv[g_dst[e]], 1.0f);
}

__global__ void finalize_dinv_kernel() {
    int i = blockIdx.x * blockDim.x + threadIdx.x;
    if (i < N_NODES) g_dinv[i] = rsqrtf(g_dinv[i]);
}

// ---------------- GEMM1: h1 = x @ W1 ; h1s = h1*dinv ; agg1 = h1s*dinv ----------------
// Tiles: 64x64, K-step 16, 256 threads, 4x4 per thread.
__global__ void __launch_bounds__(256) gemm1_kernel(
    const float* __restrict__ X,   // [N_NODES, 128]
    const float* __restrict__ W)   // [128, 256]
{
    __shared__ float As[16][64];
    __shared__ float Bs[16][64];

    const int tid = threadIdx.x;
    const int bm  = blockIdx.x * 64;
    const int bn  = blockIdx.y * 64;
    const int ty  = tid >> 4;
    const int tx  = tid & 15;

    const int ar = tid >> 2;
    const int ac = (tid & 3) * 4;
    const int bk = tid >> 4;
    const int bc = (tid & 15) * 4;

    float acc[4][4] = {};

    const int arow = bm + ar;
    for (int k0 = 0; k0 < IN_DIM; k0 += 16) {
        float4 av = make_float4(0.f, 0.f, 0.f, 0.f);
        if (arow < N_NODES)
            av = *(const float4*)(X + (size_t)arow * IN_DIM + k0 + ac);
        As[ac + 0][ar] = av.x;
        As[ac + 1][ar] = av.y;
        As[ac + 2][ar] = av.z;
        As[ac + 3][ar] = av.w;

        float4 bv = *(const float4*)(W + (size_t)(k0 + bk) * HID_DIM + bn + bc);
        *(float4*)&Bs[bk][bc] = bv;
        __syncthreads();

        #pragma unroll
        for (int k = 0; k < 16; k++) {
            float4 a = *(const float4*)&As[k][ty * 4];
            float4 b = *(const float4*)&Bs[k][tx * 4];
            float aa[4] = {a.x, a.y, a.z, a.w};
            float bb[4] = {b.x, b.y, b.z, b.w};
            #pragma unroll
            for (int i = 0; i < 4; i++)
                #pragma unroll
                for (int j = 0; j < 4; j++)
                    acc[i][j] = fmaf(aa[i], bb[j], acc[i][j]);
        }
        __syncthreads();
    }

    #pragma unroll
    for (int i = 0; i < 4; i++) {
        int r = bm + ty * 4 + i;
        if (r >= N_NODES) break;
        float di = g_dinv[r];
        int c = bn + tx * 4;
        float4 hs = make_float4(acc[i][0] * di, acc[i][1] * di,
                                acc[i][2] * di, acc[i][3] * di);
        float4 ag = make_float4(hs.x * di, hs.y * di, hs.z * di, hs.w * di);
        *(float4*)(g_h1s  + (size_t)r * HID_DIM + c) = hs;
        *(float4*)(g_agg1 + (size_t)r * HID_DIM + c) = ag;
    }
}

// ---------------- GEMM2: A = relu(agg1 + b1); out = (A@W2)*dinv^2 + b2 ----------------
__global__ void __launch_bounds__(256) gemm2_kernel(
    const float* __restrict__ W,    // [256, 128]
    const float* __restrict__ b1,   // [256]
    const float* __restrict__ b2,   // [128]
    float* __restrict__ out)        // [N_NODES, 128]
{
    __shared__ float As[16][64];
    __shared__ float Bs[16][64];

    const int tid = threadIdx.x;
    const int bm  = blockIdx.x * 64;
    const int bn  = blockIdx.y * 64;
    const int ty  = tid >> 4;
    const int tx  = tid & 15;

    const int ar = tid >> 2;
    const int ac = (tid & 3) * 4;
    const int bk = tid >> 4;
    const int bc = (tid & 15) * 4;

    float acc[4][4] = {};

    const int arow = bm + ar;
    for (int k0 = 0; k0 < HID_DIM; k0 += 16) {
        float4 av = make_float4(0.f, 0.f, 0.f, 0.f);
        if (arow < N_NODES) {
            float4 ag = *(const float4*)(g_agg1 + (size_t)arow * HID_DIM + k0 + ac);
            float4 bb = *(const float4*)(b1 + k0 + ac);
            av.x = fmaxf(ag.x + bb.x, 0.f);
            av.y = fmaxf(ag.y + bb.y, 0.f);
            av.z = fmaxf(ag.z + bb.z, 0.f);
            av.w = fmaxf(ag.w + bb.w, 0.f);
        }
        As[ac + 0][ar] = av.x;
        As[ac + 1][ar] = av.y;
        As[ac + 2][ar] = av.z;
        As[ac + 3][ar] = av.w;

        float4 bv = *(const float4*)(W + (size_t)(k0 + bk) * OUT_DIM + bn + bc);
        *(float4*)&Bs[bk][bc] = bv;
        __syncthreads();

        #pragma unroll
        for (int k = 0; k < 16; k++) {
            float4 a = *(const float4*)&As[k][ty * 4];
            float4 b = *(const float4*)&Bs[k][tx * 4];
            float aa[4] = {a.x, a.y, a.z, a.w};
            float bb[4] = {b.x, b.y, b.z, b.w};
            #pragma unroll
            for (int i = 0; i < 4; i++)
                #pragma unroll
                for (int j = 0; j < 4; j++)
                    acc[i][j] = fmaf(aa[i], bb[j], acc[i][j]);
        }
        __syncthreads();
    }

    #pragma unroll
    for (int i = 0; i < 4; i++) {
        int r = bm + ty * 4 + i;
        if (r >= N_NODES) break;
        float di = g_dinv[r];
        int c = bn + tx * 4;
        float4 bb = *(const float4*)(b2 + c);
        float4 hs = make_float4(acc[i][0] * di, acc[i][1] * di,
                                acc[i][2] * di, acc[i][3] * di);
        float4 ov = make_float4(hs.x * di + bb.x, hs.y * di + bb.y,
                                hs.z * di + bb.z, hs.w * di + bb.w);
        *(float4*)(g_h2s + (size_t)r * OUT_DIM + c) = hs;
        *(float4*)(out   + (size_t)r * OUT_DIM + c) = ov;
    }
}

// ---------------- edge scatter layer 1: g_agg1[dst] += g_h1s[src]*dinv[dst] ----------------
__global__ void __launch_bounds__(256) edge_scatter1_kernel()
{
    int warp = (blockIdx.x * blockDim.x + threadIdx.x) >> 5;
    int lane = threadIdx.x & 31;
    if (warp >= N_EDGES) return;

    int s = g_src[warp];
    int d = g_dst[warp];
    float w = g_dinv[d];

    const float4* hp = (const float4*)(g_h1s + (size_t)s * HID_DIM);
    float* ap = g_agg1 + (size_t)d * HID_DIM;

    #pragma unroll
    for (int i = lane; i < HID_DIM / 4; i += 32) {
        float4 v = hp[i];
        atomicAdd(ap + 4 * i + 0, v.x * w);
        atomicAdd(ap + 4 * i + 1, v.y * w);
        atomicAdd(ap + 4 * i + 2, v.z * w);
        atomicAdd(ap + 4 * i + 3, v.w * w);
    }
}

// ---------------- edge scatter layer 2: out[dst] += g_h2s[src]*dinv[dst] ----------------
__global__ void __launch_bounds__(256) edge_scatter2_kernel(
    float* __restrict__ out)
{
    int warp = (blockIdx.x * blockDim.x + threadIdx.x) >> 5;
    int lane = threadIdx.x & 31;
    if (warp >= N_EDGES) return;

    int s = g_src[warp];
    int d = g_dst[warp];
    float w = g_dinv[d];

    const float4* hp = (const float4*)(g_h2s + (size_t)s * OUT_DIM);
    float* ap = out + (size_t)d * OUT_DIM;

    #pragma unroll
    for (int i = lane; i < OUT_DIM / 4; i += 32) {
        float4 v = hp[i];
        atomicAdd(ap + 4 * i + 0, v.x * w);
        atomicAdd(ap + 4 * i + 1, v.y * w);
        atomicAdd(ap + 4 * i + 2, v.z * w);
        atomicAdd(ap + 4 * i + 3, v.w * w);
    }
}

// ---------------- launch ----------------
extern "C" void kernel_launch(void* const* d_in, const int* in_sizes, int n_in,
                              void* d_out, int out_size)
{
    const float* x  = (const float*)d_in[0];
    const int*   ei = (const int*)d_in[1];   // raw words; dtype detected on device
    const float* W1 = (const float*)d_in[2];
    const float* b1 = (const float*)d_in[3];
    const float* W2 = (const float*)d_in[4];
    const float* b2 = (const float*)d_in[5];
    float* out = (float*)d_out;

    // edge index normalize (handles int32 or int64 storage)
    detect_kernel<<<1, 1>>>(ei);
    convert_edges_kernel<<<(N_EDGES + 255) / 256, 256>>>(ei);

    // degree / dinv
    init_deg_kernel<<<(N_NODES + 255) / 256, 256>>>();
    count_deg_kernel<<<(N_EDGES + 255) / 256, 256>>>();
    finalize_dinv_kernel<<<(N_NODES + 255) / 256, 256>>>();

    // layer 1
    dim3 g1((N_NODES + 63) / 64, HID_DIM / 64);
    gemm1_kernel<<<g1, 256>>>(x, W1);
    {
        int blocks = (N_EDGES + 7) / 8;   // 8 warps (edges) per 256-thread block
        edge_scatter1_kernel<<<blocks, 256>>>();
    }

    // layer 2 (fused relu(agg1+b1) on A-load; out initialized with self-loop + b2)
    dim3 g2((N_NODES + 63) / 64, OUT_DIM / 64);
    gemm2_kernel<<<g2, 256>>>(W2, b1, b2, out);
    {
        int blocks = (N_EDGES + 7) / 8;
        edge_scatter2_kernel<<<blocks, 256>>>(out);
    }
}

// round 4
// speedup vs baseline: 2.1037x; 2.1037x over previous
#include <cuda_runtime.h>
#include <math.h>

#define N_NODES 50000
#define N_EDGES 800000
#define IN_DIM  128
#define HID_DIM 256
#define OUT_DIM 128

#define SCAN_THREADS 1024
#define SCAN_CHUNK   ((N_NODES + SCAN_THREADS - 1) / SCAN_THREADS)   // 49

// ---------------- scratch (device globals: no allocs allowed) ----------------
__device__ int   g_is64;
__device__ int   g_deg    [N_NODES];        // in-degree (edges only)
__device__ int   g_rowstart[N_NODES + 1];   // CSR row offsets (by dst)
__device__ int   g_cursor [N_NODES];        // fill cursors
__device__ int   g_csr_src[N_EDGES];        // src ids grouped by dst
__device__ int   g_dst    [N_EDGES];        // dst per edge (for hist/fill)
__device__ int   g_src    [N_EDGES];        // src per edge
__device__ float g_dinv   [N_NODES];        // rsqrt(deg+1)
__device__ float g_h1s    [N_NODES * HID_DIM];   // (x@W1) * dinv[row]
__device__ float g_agg1   [N_NODES * HID_DIM];   // layer-1 aggregation (normalized)
__device__ float g_h2s    [N_NODES * OUT_DIM];   // (relu(agg1+b1)@W2) * dinv[row]

// ---------------- edge index dtype detection ----------------
__global__ void detect_kernel(const int* __restrict__ ei_raw) {
    int ornz = 0;
    #pragma unroll 8
    for (int i = 0; i < 512; i++) ornz |= ei_raw[2 * i + 1];
    g_is64 = (ornz == 0) ? 1 : 0;
}

__global__ void zero_deg_kernel() {
    int i = blockIdx.x * blockDim.x + threadIdx.x;
    if (i < N_NODES) g_deg[i] = 0;
}

// convert (int32 or int64 storage) + degree histogram
__global__ void convert_edges_kernel(const int* __restrict__ ei_raw) {
    int e = blockIdx.x * blockDim.x + threadIdx.x;
    if (e >= N_EDGES) return;
    int s, d;
    if (g_is64) {
        const long long* p = (const long long*)ei_raw;
        s = (int)p[e];
        d = (int)p[N_EDGES + e];
    } else {
        s = ei_raw[e];
        d = ei_raw[N_EDGES + e];
    }
    g_src[e] = s;
    g_dst[e] = d;
    atomicAdd(&g_deg[d], 1);
}

// single-block exclusive scan of g_deg -> rowstart/cursor ; also dinv
__global__ void __launch_bounds__(SCAN_THREADS) scan_kernel() {
    __shared__ int sh[SCAN_THREADS];
    int tid = threadIdx.x;
    int lo = tid * SCAN_CHUNK;
    int hi = lo + SCAN_CHUNK; if (hi > N_NODES) hi = N_NODES;

    int s = 0;
    for (int i = lo; i < hi; i++) s += g_deg[i];
    sh[tid] = s;
    __syncthreads();

    // Hillis-Steele inclusive scan over 1024 partials
    for (int ofs = 1; ofs < SCAN_THREADS; ofs <<= 1) {
        int v = (tid >= ofs) ? sh[tid - ofs] : 0;
        __syncthreads();
        sh[tid] += v;
        __syncthreads();
    }

    int run = sh[tid] - s;  // exclusive base for this chunk
    for (int i = lo; i < hi; i++) {
        int d = g_deg[i];
        g_rowstart[i] = run;
        g_cursor[i]   = run;
        g_dinv[i]     = rsqrtf((float)d + 1.0f);
        run += d;
    }
    if (tid == SCAN_THREADS - 1) g_rowstart[N_NODES] = run;
}

__global__ void fill_csr_kernel() {
    int e = blockIdx.x * blockDim.x + threadIdx.x;
    if (e >= N_EDGES) return;
    int pos = atomicAdd(&g_cursor[g_dst[e]], 1);
    g_csr_src[pos] = g_src[e];
}

// ---------------- GEMM1: g_h1s = (x @ W1) * dinv[row] ----------------
// Tiles: 64x64, K-step 16, 256 threads, 4x4 per thread.
__global__ void __launch_bounds__(256) gemm1_kernel(
    const float* __restrict__ X,   // [N_NODES, 128]
    const float* __restrict__ W)   // [128, 256]
{
    __shared__ float As[16][64];
    __shared__ float Bs[16][64];

    const int tid = threadIdx.x;
    const int bm  = blockIdx.x * 64;
    const int bn  = blockIdx.y * 64;
    const int ty  = tid >> 4;
    const int tx  = tid & 15;

    const int ar = tid >> 2;
    const int ac = (tid & 3) * 4;
    const int bk = tid >> 4;
    const int bc = (tid & 15) * 4;

    float acc[4][4] = {};

    const int arow = bm + ar;
    for (int k0 = 0; k0 < IN_DIM; k0 += 16) {
        float4 av = make_float4(0.f, 0.f, 0.f, 0.f);
        if (arow < N_NODES)
            av = *(const float4*)(X + (size_t)arow * IN_DIM + k0 + ac);
        As[ac + 0][ar] = av.x;
        As[ac + 1][ar] = av.y;
        As[ac + 2][ar] = av.z;
        As[ac + 3][ar] = av.w;

        float4 bv = *(const float4*)(W + (size_t)(k0 + bk) * HID_DIM + bn + bc);
        *(float4*)&Bs[bk][bc] = bv;
        __syncthreads();

        #pragma unroll
        for (int k = 0; k < 16; k++) {
            float4 a = *(const float4*)&As[k][ty * 4];
            float4 b = *(const float4*)&Bs[k][tx * 4];
            float aa[4] = {a.x, a.y, a.z, a.w};
            float bb[4] = {b.x, b.y, b.z, b.w};
            #pragma unroll
            for (int i = 0; i < 4; i++)
                #pragma unroll
                for (int j = 0; j < 4; j++)
                    acc[i][j] = fmaf(aa[i], bb[j], acc[i][j]);
        }
        __syncthreads();
    }

    #pragma unroll
    for (int i = 0; i < 4; i++) {
        int r = bm + ty * 4 + i;
        if (r >= N_NODES) break;
        float di = g_dinv[r];
        int c = bn + tx * 4;
        float4 hs = make_float4(acc[i][0] * di, acc[i][1] * di,
                                acc[i][2] * di, acc[i][3] * di);
        *(float4*)(g_h1s + (size_t)r * HID_DIM + c) = hs;
    }
}

// ---------------- agg1: g_agg1[d] = dinv[d] * (sum_{src in in(d)} h1s[src] + h1s[d]) ----------------
// one warp per node; lane covers cols {lane*4, 128+lane*4}
__global__ void __launch_bounds__(256) agg1_kernel()
{
    int node = ((blockIdx.x * blockDim.x + threadIdx.x) >> 5);
    int lane = threadIdx.x & 31;
    if (node >= N_NODES) return;

    int beg = g_rowstart[node];
    int end = g_rowstart[node + 1];
    int c0 = lane * 4;
    int c1 = 128 + lane * 4;

    // self term
    float4 a0 = *(const float4*)(g_h1s + (size_t)node * HID_DIM + c0);
    float4 a1 = *(const float4*)(g_h1s + (size_t)node * HID_DIM + c1);

    int e = beg;
    for (; e + 1 < end; e += 2) {
        int s0 = g_csr_src[e];
        int s1 = g_csr_src[e + 1];
        float4 v00 = *(const float4*)(g_h1s + (size_t)s0 * HID_DIM + c0);
        float4 v01 = *(const float4*)(g_h1s + (size_t)s0 * HID_DIM + c1);
        float4 v10 = *(const float4*)(g_h1s + (size_t)s1 * HID_DIM + c0);
        float4 v11 = *(const float4*)(g_h1s + (size_t)s1 * HID_DIM + c1);
        a0.x += v00.x + v10.x; a0.y += v00.y + v10.y;
        a0.z += v00.z + v10.z; a0.w += v00.w + v10.w;
        a1.x += v01.x + v11.x; a1.y += v01.y + v11.y;
        a1.z += v01.z + v11.z; a1.w += v01.w + v11.w;
    }
    if (e < end) {
        int s0 = g_csr_src[e];
        float4 v00 = *(const float4*)(g_h1s + (size_t)s0 * HID_DIM + c0);
        float4 v01 = *(const float4*)(g_h1s + (size_t)s0 * HID_DIM + c1);
        a0.x += v00.x; a0.y += v00.y; a0.z += v00.z; a0.w += v00.w;
        a1.x += v01.x; a1.y += v01.y; a1.z += v01.z; a1.w += v01.w;
    }

    float w = g_dinv[node];
    a0.x *= w; a0.y *= w; a0.z *= w; a0.w *= w;
    a1.x *= w; a1.y *= w; a1.z *= w; a1.w *= w;
    *(float4*)(g_agg1 + (size_t)node * HID_DIM + c0) = a0;
    *(float4*)(g_agg1 + (size_t)node * HID_DIM + c1) = a1;
}

// ---------------- GEMM2: A = relu(agg1 + b1); g_h2s = (A@W2)*dinv[row] ----------------
__global__ void __launch_bounds__(256) gemm2_kernel(
    const float* __restrict__ W,    // [256, 128]
    const float* __restrict__ b1)   // [256]
{
    __shared__ float As[16][64];
    __shared__ float Bs[16][64];

    const int tid = threadIdx.x;
    const int bm  = blockIdx.x * 64;
    const int bn  = blockIdx.y * 64;
    const int ty  = tid >> 4;
    const int tx  = tid & 15;

    const int ar = tid >> 2;
    const int ac = (tid & 3) * 4;
    const int bk = tid >> 4;
    const int bc = (tid & 15) * 4;

    float acc[4][4] = {};

    const int arow = bm + ar;
    for (int k0 = 0; k0 < HID_DIM; k0 += 16) {
        float4 av = make_float4(0.f, 0.f, 0.f, 0.f);
        if (arow < N_NODES) {
            float4 ag = *(const float4*)(g_agg1 + (size_t)arow * HID_DIM + k0 + ac);
            float4 bb = *(const float4*)(b1 + k0 + ac);
            av.x = fmaxf(ag.x + bb.x, 0.f);
            av.y = fmaxf(ag.y + bb.y, 0.f);
            av.z = fmaxf(ag.z + bb.z, 0.f);
            av.w = fmaxf(ag.w + bb.w, 0.f);
        }
        As[ac + 0][ar] = av.x;
        As[ac + 1][ar] = av.y;
        As[ac + 2][ar] = av.z;
        As[ac + 3][ar] = av.w;

        float4 bv = *(const float4*)(W + (size_t)(k0 + bk) * OUT_DIM + bn + bc);
        *(float4*)&Bs[bk][bc] = bv;
        __syncthreads();

        #pragma unroll
        for (int k = 0; k < 16; k++) {
            float4 a = *(const float4*)&As[k][ty * 4];
            float4 b = *(const float4*)&Bs[k][tx * 4];
            float aa[4] = {a.x, a.y, a.z, a.w};
            float bb[4] = {b.x, b.y, b.z, b.w};
            #pragma unroll
            for (int i = 0; i < 4; i++)
                #pragma unroll
                for (int j = 0; j < 4; j++)
                    acc[i][j] = fmaf(aa[i], bb[j], acc[i][j]);
        }
        __syncthreads();
    }

    #pragma unroll
    for (int i = 0; i < 4; i++) {
        int r = bm + ty * 4 + i;
        if (r >= N_NODES) break;
        float di = g_dinv[r];
        int c = bn + tx * 4;
        float4 hs = make_float4(acc[i][0] * di, acc[i][1] * di,
                                acc[i][2] * di, acc[i][3] * di);
        *(float4*)(g_h2s + (size_t)r * OUT_DIM + c) = hs;
    }
}

// ---------------- agg2: out[d] = dinv[d]*(sum h2s[src] + h2s[d]) + b2 ----------------
__global__ void __launch_bounds__(256) agg2_kernel(
    const float* __restrict__ b2,
    float* __restrict__ out)
{
    int node = ((blockIdx.x * blockDim.x + threadIdx.x) >> 5);
    int lane = threadIdx.x & 31;
    if (node >= N_NODES) return;

    int beg = g_rowstart[node];
    int end = g_rowstart[node + 1];
    int c0 = lane * 4;

    float4 a0 = *(const float4*)(g_h2s + (size_t)node * OUT_DIM + c0);

    int e = beg;
    for (; e + 1 < end; e += 2) {
        int s0 = g_csr_src[e];
        int s1 = g_csr_src[e + 1];
        float4 v0 = *(const float4*)(g_h2s + (size_t)s0 * OUT_DIM + c0);
        float4 v1 = *(const float4*)(g_h2s + (size_t)s1 * OUT_DIM + c0);
        a0.x += v0.x + v1.x; a0.y += v0.y + v1.y;
        a0.z += v0.z + v1.z; a0.w += v0.w + v1.w;
    }
    if (e < end) {
        int s0 = g_csr_src[e];
        float4 v0 = *(const float4*)(g_h2s + (size_t)s0 * OUT_DIM + c0);
        a0.x += v0.x; a0.y += v0.y; a0.z += v0.z; a0.w += v0.w;
    }

    float w = g_dinv[node];
    float4 bb = *(const float4*)(b2 + c0);
    a0.x = a0.x * w + bb.x;
    a0.y = a0.y * w + bb.y;
    a0.z = a0.z * w + bb.z;
    a0.w = a0.w * w + bb.w;
    *(float4*)(out + (size_t)node * OUT_DIM + c0) = a0;
}

// ---------------- launch ----------------
extern "C" void kernel_launch(void* const* d_in, const int* in_sizes, int n_in,
                              void* d_out, int out_size)
{
    const float* x  = (const float*)d_in[0];
    const int*   ei = (const int*)d_in[1];   // raw words; dtype detected on device
    const float* W1 = (const float*)d_in[2];
    const float* b1 = (const float*)d_in[3];
    const float* W2 = (const float*)d_in[4];
    const float* b2 = (const float*)d_in[5];
    float* out = (float*)d_out;

    // CSR build
    detect_kernel<<<1, 1>>>(ei);
    zero_deg_kernel<<<(N_NODES + 255) / 256, 256>>>();
    convert_edges_kernel<<<(N_EDGES + 255) / 256, 256>>>(ei);
    scan_kernel<<<1, SCAN_THREADS>>>();
    fill_csr_kernel<<<(N_EDGES + 255) / 256, 256>>>();

    // layer 1
    dim3 g1((N_NODES + 63) / 64, HID_DIM / 64);
    gemm1_kernel<<<g1, 256>>>(x, W1);
    agg1_kernel<<<(N_NODES + 7) / 8, 256>>>();

    // layer 2
    dim3 g2((N_NODES + 63) / 64, OUT_DIM / 64);
    gemm2_kernel<<<g2, 256>>>(W2, b1);
    agg2_kernel<<<(N_NODES + 7) / 8, 256>>>(b2, out);
}

// round 5
// speedup vs baseline: 2.6622x; 1.2655x over previous
#include <cuda_runtime.h>
#include <math.h>

#define N_NODES 50000
#define N_EDGES 800000
#define IN_DIM  128
#define HID_DIM 256
#define OUT_DIM 128

#define SCAN_BLK 256
#define N_SCAN_BLOCKS ((N_NODES + SCAN_BLK - 1) / SCAN_BLK)   // 196

// ---------------- scratch (device globals: no allocs allowed) ----------------
__device__ int   g_is64;
__device__ int   g_deg     [N_NODES];        // in-degree (edges only)
__device__ int   g_blocksum[N_SCAN_BLOCKS];  // per-block deg sums
__device__ int   g_blockbase[N_SCAN_BLOCKS]; // exclusive scan of blocksums
__device__ int   g_rowstart[N_NODES + 1];    // CSR row offsets (by dst)
__device__ int   g_cursor  [N_NODES];        // fill cursors
__device__ int   g_csr_src [N_EDGES];        // src ids grouped by dst
__device__ int   g_dst     [N_EDGES];        // dst per edge
__device__ int   g_src     [N_EDGES];        // src per edge
__device__ float g_dinv    [N_NODES];        // rsqrt(deg+1)
__device__ float g_h1s     [N_NODES * HID_DIM];   // (x@W1) * dinv[row]
__device__ float g_agg1    [N_NODES * HID_DIM];   // layer-1 aggregation (normalized)
__device__ float g_h2s     [N_NODES * OUT_DIM];   // (relu(agg1+b1)@W2) * dinv[row]

// ---------------- edge index dtype detection ----------------
__global__ void detect_kernel(const int* __restrict__ ei_raw) {
    int ornz = 0;
    #pragma unroll 8
    for (int i = 0; i < 512; i++) ornz |= ei_raw[2 * i + 1];
    g_is64 = (ornz == 0) ? 1 : 0;
}

__global__ void zero_deg_kernel() {
    int i = blockIdx.x * blockDim.x + threadIdx.x;
    if (i < N_NODES) g_deg[i] = 0;
}

// convert (int32 or int64 storage) + degree histogram
__global__ void convert_edges_kernel(const int* __restrict__ ei_raw) {
    int e = blockIdx.x * blockDim.x + threadIdx.x;
    if (e >= N_EDGES) return;
    int s, d;
    if (g_is64) {
        const long long* p = (const long long*)ei_raw;
        s = (int)p[e];
        d = (int)p[N_EDGES + e];
    } else {
        s = ei_raw[e];
        d = ei_raw[N_EDGES + e];
    }
    g_src[e] = s;
    g_dst[e] = d;
    atomicAdd(&g_deg[d], 1);
}

// ---------------- parallel exclusive scan over g_deg (3 kernels) ----------------
__global__ void __launch_bounds__(SCAN_BLK) block_sum_kernel() {
    __shared__ int sh[SCAN_BLK / 32];
    int i = blockIdx.x * SCAN_BLK + threadIdx.x;
    int v = (i < N_NODES) ? g_deg[i] : 0;
    // warp reduce
    #pragma unroll
    for (int o = 16; o > 0; o >>= 1) v += __shfl_down_sync(0xffffffffu, v, o);
    if ((threadIdx.x & 31) == 0) sh[threadIdx.x >> 5] = v;
    __syncthreads();
    if (threadIdx.x < SCAN_BLK / 32) {
        int w = sh[threadIdx.x];
        #pragma unroll
        for (int o = SCAN_BLK / 64; o > 0; o >>= 1) w += __shfl_down_sync(0xffu, w, o);
        if (threadIdx.x == 0) g_blocksum[blockIdx.x] = w;
    }
}

__global__ void __launch_bounds__(256) scan_blocksums_kernel() {
    __shared__ int sh[256];
    int tid = threadIdx.x;
    int v = (tid < N_SCAN_BLOCKS) ? g_blocksum[tid] : 0;
    sh[tid] = v;
    __syncthreads();
    for (int ofs = 1; ofs < 256; ofs <<= 1) {
        int u = (tid >= ofs) ? sh[tid - ofs] : 0;
        __syncthreads();
        sh[tid] += u;
        __syncthreads();
    }
    if (tid < N_SCAN_BLOCKS) g_blockbase[tid] = sh[tid] - v;   // exclusive
    if (tid == N_SCAN_BLOCKS - 1) g_rowstart[N_NODES] = sh[tid];
}

__global__ void __launch_bounds__(SCAN_BLK) write_offsets_kernel() {
    __shared__ int sh[SCAN_BLK];
    int tid = threadIdx.x;
    int i = blockIdx.x * SCAN_BLK + tid;
    int d = (i < N_NODES) ? g_deg[i] : 0;
    sh[tid] = d;
    __syncthreads();
    for (int ofs = 1; ofs < SCAN_BLK; ofs <<= 1) {
        int u = (tid >= ofs) ? sh[tid - ofs] : 0;
        __syncthreads();
        sh[tid] += u;
        __syncthreads();
    }
    if (i < N_NODES) {
        int start = g_blockbase[blockIdx.x] + sh[tid] - d;  // exclusive
        g_rowstart[i] = start;
        g_cursor[i]   = start;
        g_dinv[i]     = rsqrtf((float)d + 1.0f);
    }
}

__global__ void fill_csr_kernel() {
    int e = blockIdx.x * blockDim.x + threadIdx.x;
    if (e >= N_EDGES) return;
    int pos = atomicAdd(&g_cursor[g_dst[e]], 1);
    g_csr_src[pos] = g_src[e];
}

// ---------------- GEMM1: g_h1s = (x @ W1) * dinv[row] ----------------
// Tiles: 64x64, K-step 16, 256 threads, 4x4 per thread.
__global__ void __launch_bounds__(256) gemm1_kernel(
    const float* __restrict__ X,   // [N_NODES, 128]
    const float* __restrict__ W)   // [128, 256]
{
    __shared__ float As[16][64];
    __shared__ float Bs[16][64];

    const int tid = threadIdx.x;
    const int bm  = blockIdx.x * 64;
    const int bn  = blockIdx.y * 64;
    const int ty  = tid >> 4;
    const int tx  = tid & 15;

    const int ar = tid >> 2;
    const int ac = (tid & 3) * 4;
    const int bk = tid >> 4;
    const int bc = (tid & 15) * 4;

    float acc[4][4] = {};

    const int arow = bm + ar;
    for (int k0 = 0; k0 < IN_DIM; k0 += 16) {
        float4 av = make_float4(0.f, 0.f, 0.f, 0.f);
        if (arow < N_NODES)
            av = *(const float4*)(X + (size_t)arow * IN_DIM + k0 + ac);
        As[ac + 0][ar] = av.x;
        As[ac + 1][ar] = av.y;
        As[ac + 2][ar] = av.z;
        As[ac + 3][ar] = av.w;

        float4 bv = *(const float4*)(W + (size_t)(k0 + bk) * HID_DIM + bn + bc);
        *(float4*)&Bs[bk][bc] = bv;
        __syncthreads();

        #pragma unroll
        for (int k = 0; k < 16; k++) {
            float4 a = *(const float4*)&As[k][ty * 4];
            float4 b = *(const float4*)&Bs[k][tx * 4];
            float aa[4] = {a.x, a.y, a.z, a.w};
            float bb[4] = {b.x, b.y, b.z, b.w};
            #pragma unroll
            for (int i = 0; i < 4; i++)
                #pragma unroll
                for (int j = 0; j < 4; j++)
                    acc[i][j] = fmaf(aa[i], bb[j], acc[i][j]);
        }
        __syncthreads();
    }

    #pragma unroll
    for (int i = 0; i < 4; i++) {
        int r = bm + ty * 4 + i;
        if (r >= N_NODES) break;
        float di = g_dinv[r];
        int c = bn + tx * 4;
        float4 hs = make_float4(acc[i][0] * di, acc[i][1] * di,
                                acc[i][2] * di, acc[i][3] * di);
        *(float4*)(g_h1s + (size_t)r * HID_DIM + c) = hs;
    }
}

// ---------------- agg1: g_agg1[d] = dinv[d] * (sum_{src in in(d)} h1s[src] + h1s[d]) ----------------
__global__ void __launch_bounds__(256) agg1_kernel()
{
    int node = ((blockIdx.x * blockDim.x + threadIdx.x) >> 5);
    int lane = threadIdx.x & 31;
    if (node >= N_NODES) return;

    int beg = g_rowstart[node];
    int end = g_rowstart[node + 1];
    int c0 = lane * 4;
    int c1 = 128 + lane * 4;

    float4 a0 = *(const float4*)(g_h1s + (size_t)node * HID_DIM + c0);
    float4 a1 = *(const float4*)(g_h1s + (size_t)node * HID_DIM + c1);

    int e = beg;
    for (; e + 1 < end; e += 2) {
        int s0 = g_csr_src[e];
        int s1 = g_csr_src[e + 1];
        float4 v00 = *(const float4*)(g_h1s + (size_t)s0 * HID_DIM + c0);
        float4 v01 = *(const float4*)(g_h1s + (size_t)s0 * HID_DIM + c1);
        float4 v10 = *(const float4*)(g_h1s + (size_t)s1 * HID_DIM + c0);
        float4 v11 = *(const float4*)(g_h1s + (size_t)s1 * HID_DIM + c1);
        a0.x += v00.x + v10.x; a0.y += v00.y + v10.y;
        a0.z += v00.z + v10.z; a0.w += v00.w + v10.w;
        a1.x += v01.x + v11.x; a1.y += v01.y + v11.y;
        a1.z += v01.z + v11.z; a1.w += v01.w + v11.w;
    }
    if (e < end) {
        int s0 = g_csr_src[e];
        float4 v00 = *(const float4*)(g_h1s + (size_t)s0 * HID_DIM + c0);
        float4 v01 = *(const float4*)(g_h1s + (size_t)s0 * HID_DIM + c1);
        a0.x += v00.x; a0.y += v00.y; a0.z += v00.z; a0.w += v00.w;
        a1.x += v01.x; a1.y += v01.y; a1.z += v01.z; a1.w += v01.w;
    }

    float w = g_dinv[node];
    a0.x *= w; a0.y *= w; a0.z *= w; a0.w *= w;
    a1.x *= w; a1.y *= w; a1.z *= w; a1.w *= w;
    *(float4*)(g_agg1 + (size_t)node * HID_DIM + c0) = a0;
    *(float4*)(g_agg1 + (size_t)node * HID_DIM + c1) = a1;
}

// ---------------- GEMM2: A = relu(agg1 + b1); g_h2s = (A@W2)*dinv[row] ----------------
__global__ void __launch_bounds__(256) gemm2_kernel(
    const float* __restrict__ W,    // [256, 128]
    const float* __restrict__ b1)   // [256]
{
    __shared__ float As[16][64];
    __shared__ float Bs[16][64];

    const int tid = threadIdx.x;
    const int bm  = blockIdx.x * 64;
    const int bn  = blockIdx.y * 64;
    const int ty  = tid >> 4;
    const int tx  = tid & 15;

    const int ar = tid >> 2;
    const int ac = (tid & 3) * 4;
    const int bk = tid >> 4;
    const int bc = (tid & 15) * 4;

    float acc[4][4] = {};

    const int arow = bm + ar;
    for (int k0 = 0; k0 < HID_DIM; k0 += 16) {
        float4 av = make_float4(0.f, 0.f, 0.f, 0.f);
        if (arow < N_NODES) {
            float4 ag = *(const float4*)(g_agg1 + (size_t)arow * HID_DIM + k0 + ac);
            float4 bb = *(const float4*)(b1 + k0 + ac);
            av.x = fmaxf(ag.x + bb.x, 0.f);
            av.y = fmaxf(ag.y + bb.y, 0.f);
            av.z = fmaxf(ag.z + bb.z, 0.f);
            av.w = fmaxf(ag.w + bb.w, 0.f);
        }
        As[ac + 0][ar] = av.x;
        As[ac + 1][ar] = av.y;
        As[ac + 2][ar] = av.z;
        As[ac + 3][ar] = av.w;

        float4 bv = *(const float4*)(W + (size_t)(k0 + bk) * OUT_DIM + bn + bc);
        *(float4*)&Bs[bk][bc] = bv;
        __syncthreads();

        #pragma unroll
        for (int k = 0; k < 16; k++) {
            float4 a = *(const float4*)&As[k][ty * 4];
            float4 b = *(const float4*)&Bs[k][tx * 4];
            float aa[4] = {a.x, a.y, a.z, a.w};
            float bb[4] = {b.x, b.y, b.z, b.w};
            #pragma unroll
            for (int i = 0; i < 4; i++)
                #pragma unroll
                for (int j = 0; j < 4; j++)
                    acc[i][j] = fmaf(aa[i], bb[j], acc[i][j]);
        }
        __syncthreads();
    }

    #pragma unroll
    for (int i = 0; i < 4; i++) {
        int r = bm + ty * 4 + i;
        if (r >= N_NODES) break;
        float di = g_dinv[r];
        int c = bn + tx * 4;
        float4 hs = make_float4(acc[i][0] * di, acc[i][1] * di,
                                acc[i][2] * di, acc[i][3] * di);
        *(float4*)(g_h2s + (size_t)r * OUT_DIM + c) = hs;
    }
}

// ---------------- agg2: out[d] = dinv[d]*(sum h2s[src] + h2s[d]) + b2 ----------------
__global__ void __launch_bounds__(256) agg2_kernel(
    const float* __restrict__ b2,
    float* __restrict__ out)
{
    int node = ((blockIdx.x * blockDim.x + threadIdx.x) >> 5);
    int lane = threadIdx.x & 31;
    if (node >= N_NODES) return;

    int beg = g_rowstart[node];
    int end = g_rowstart[node + 1];
    int c0 = lane * 4;

    float4 a0 = *(const float4*)(g_h2s + (size_t)node * OUT_DIM + c0);

    int e = beg;
    for (; e + 1 < end; e += 2) {
        int s0 = g_csr_src[e];
        int s1 = g_csr_src[e + 1];
        float4 v0 = *(const float4*)(g_h2s + (size_t)s0 * OUT_DIM + c0);
        float4 v1 = *(const float4*)(g_h2s + (size_t)s1 * OUT_DIM + c0);
        a0.x += v0.x + v1.x; a0.y += v0.y + v1.y;
        a0.z += v0.z + v1.z; a0.w += v0.w + v1.w;
    }
    if (e < end) {
        int s0 = g_csr_src[e];
        float4 v0 = *(const float4*)(g_h2s + (size_t)s0 * OUT_DIM + c0);
        a0.x += v0.x; a0.y += v0.y; a0.z += v0.z; a0.w += v0.w;
    }

    float w = g_dinv[node];
    float4 bb = *(const float4*)(b2 + c0);
    a0.x = a0.x * w + bb.x;
    a0.y = a0.y * w + bb.y;
    a0.z = a0.z * w + bb.z;
    a0.w = a0.w * w + bb.w;
    *(float4*)(out + (size_t)node * OUT_DIM + c0) = a0;
}

// ---------------- launch ----------------
extern "C" void kernel_launch(void* const* d_in, const int* in_sizes, int n_in,
                              void* d_out, int out_size)
{
    const float* x  = (const float*)d_in[0];
    const int*   ei = (const int*)d_in[1];   // raw words; dtype detected on device
    const float* W1 = (const float*)d_in[2];
    const float* b1 = (const float*)d_in[3];
    const float* W2 = (const float*)d_in[4];
    const float* b2 = (const float*)d_in[5];
    float* out = (float*)d_out;

    // CSR build
    detect_kernel<<<1, 1>>>(ei);
    zero_deg_kernel<<<(N_NODES + 255) / 256, 256>>>();
    convert_edges_kernel<<<(N_EDGES + 255) / 256, 256>>>(ei);
    block_sum_kernel<<<N_SCAN_BLOCKS, SCAN_BLK>>>();
    scan_blocksums_kernel<<<1, 256>>>();
    write_offsets_kernel<<<N_SCAN_BLOCKS, SCAN_BLK>>>();
    fill_csr_kernel<<<(N_EDGES + 255) / 256, 256>>>();

    // layer 1
    dim3 g1((N_NODES + 63) / 64, HID_DIM / 64);
    gemm1_kernel<<<g1, 256>>>(x, W1);
    agg1_kernel<<<(N_NODES + 7) / 8, 256>>>();

    // layer 2
    dim3 g2((N_NODES + 63) / 64, OUT_DIM / 64);
    gemm2_kernel<<<g2, 256>>>(W2, b1);
    agg2_kernel<<<(N_NODES + 7) / 8, 256>>>(b2, out);
}

// round 8
// speedup vs baseline: 2.8335x; 1.0644x over previous
#include <cuda_runtime.h>
#include <math.h>

#define N_NODES 50000
#define N_EDGES 800000
#define IN_DIM  128
#define HID_DIM 256
#define OUT_DIM 128

#define SCAN_BLK 256
#define N_SCAN_BLOCKS ((N_NODES + SCAN_BLK - 1) / SCAN_BLK)   // 196

// ---------------- scratch (device globals: no allocs allowed) ----------------
__device__ int   g_is64;
__device__ int   g_deg     [N_NODES];
__device__ int   g_blocksum[N_SCAN_BLOCKS];
__device__ int   g_blockbase[N_SCAN_BLOCKS];
__device__ int   g_rowstart[N_NODES + 1];
__device__ int   g_cursor  [N_NODES];
__device__ int   g_csr_src [N_EDGES];
__device__ int   g_dst     [N_EDGES];
__device__ int   g_src     [N_EDGES];
__device__ float g_dinv    [N_NODES];
__device__ float g_aggx    [N_NODES * IN_DIM];    // normalized aggregation of x
__device__ float g_h1      [N_NODES * HID_DIM];   // aggx @ W1   (pre-bias/relu)
__device__ float g_h2s     [N_NODES * OUT_DIM];   // (relu(h1+b1)@W2) * dinv[row]

// ---------------- edge index dtype detection ----------------
__global__ void detect_kernel(const int* __restrict__ ei_raw) {
    int ornz = 0;
    #pragma unroll 8
    for (int i = 0; i < 512; i++) ornz |= ei_raw[2 * i + 1];
    g_is64 = (ornz == 0) ? 1 : 0;
}

__global__ void zero_deg_kernel() {
    int i = blockIdx.x * blockDim.x + threadIdx.x;
    if (i < N_NODES) g_deg[i] = 0;
}

__global__ void convert_edges_kernel(const int* __restrict__ ei_raw) {
    int e = blockIdx.x * blockDim.x + threadIdx.x;
    if (e >= N_EDGES) return;
    int s, d;
    if (g_is64) {
        const long long* p = (const long long*)ei_raw;
        s = (int)p[e];
        d = (int)p[N_EDGES + e];
    } else {
        s = ei_raw[e];
        d = ei_raw[N_EDGES + e];
    }
    g_src[e] = s;
    g_dst[e] = d;
    atomicAdd(&g_deg[d], 1);
}

// ---------------- parallel exclusive scan over g_deg ----------------
__global__ void __launch_bounds__(SCAN_BLK) block_sum_kernel() {
    __shared__ int sh[SCAN_BLK / 32];
    int i = blockIdx.x * SCAN_BLK + threadIdx.x;
    int v = (i < N_NODES) ? g_deg[i] : 0;
    #pragma unroll
    for (int o = 16; o > 0; o >>= 1) v += __shfl_down_sync(0xffffffffu, v, o);
    if ((threadIdx.x & 31) == 0) sh[threadIdx.x >> 5] = v;
    __syncthreads();
    if (threadIdx.x < SCAN_BLK / 32) {
        int w = sh[threadIdx.x];
        #pragma unroll
        for (int o = SCAN_BLK / 64; o > 0; o >>= 1) w += __shfl_down_sync(0xffu, w, o);
        if (threadIdx.x == 0) g_blocksum[blockIdx.x] = w;
    }
}

__global__ void __launch_bounds__(256) scan_blocksums_kernel() {
    __shared__ int sh[256];
    int tid = threadIdx.x;
    int v = (tid < N_SCAN_BLOCKS) ? g_blocksum[tid] : 0;
    sh[tid] = v;
    __syncthreads();
    for (int ofs = 1; ofs < 256; ofs <<= 1) {
        int u = (tid >= ofs) ? sh[tid - ofs] : 0;
        __syncthreads();
        sh[tid] += u;
        __syncthreads();
    }
    if (tid < N_SCAN_BLOCKS) g_blockbase[tid] = sh[tid] - v;
    if (tid == N_SCAN_BLOCKS - 1) g_rowstart[N_NODES] = sh[tid];
}

__global__ void __launch_bounds__(SCAN_BLK) write_offsets_kernel() {
    __shared__ int sh[SCAN_BLK];
    int tid = threadIdx.x;
    int i = blockIdx.x * SCAN_BLK + tid;
    int d = (i < N_NODES) ? g_deg[i] : 0;
    sh[tid] = d;
    __syncthreads();
    for (int ofs = 1; ofs < SCAN_BLK; ofs <<= 1) {
        int u = (tid >= ofs) ? sh[tid - ofs] : 0;
        __syncthreads();
        sh[tid] += u;
        __syncthreads();
    }
    if (i < N_NODES) {
        int start = g_blockbase[blockIdx.x] + sh[tid] - d;
        g_rowstart[i] = start;
        g_cursor[i]   = start;
        g_dinv[i]     = rsqrtf((float)d + 1.0f);
    }
}

__global__ void fill_csr_kernel() {
    int e = blockIdx.x * blockDim.x + threadIdx.x;
    if (e >= N_EDGES) return;
    int pos = atomicAdd(&g_cursor[g_dst[e]], 1);
    g_csr_src[pos] = g_src[e];
}

// ---------------- aggX: g_aggx[d] = dinv[d]*(sum dinv[s]*x[s] + dinv[d]*x[d]) ----------------
__global__ void __launch_bounds__(256) aggx_kernel(const float* __restrict__ X)
{
    int node = ((blockIdx.x * blockDim.x + threadIdx.x) >> 5);
    int lane = threadIdx.x & 31;
    if (node >= N_NODES) return;

    int beg = g_rowstart[node];
    int end = g_rowstart[node + 1];
    int c = lane * 4;

    float wd = g_dinv[node];
    float4 v = *(const float4*)(X + (size_t)node * IN_DIM + c);
    float4 a = make_float4(v.x * wd, v.y * wd, v.z * wd, v.w * wd);

    int e = beg;
    for (; e + 1 < end; e += 2) {
        int s0 = g_csr_src[e];
        int s1 = g_csr_src[e + 1];
        float w0 = g_dinv[s0];
        float w1 = g_dinv[s1];
        float4 v0 = *(const float4*)(X + (size_t)s0 * IN_DIM + c);
        float4 v1 = *(const float4*)(X + (size_t)s1 * IN_DIM + c);
        a.x = fmaf(v0.x, w0, fmaf(v1.x, w1, a.x));
        a.y = fmaf(v0.y, w0, fmaf(v1.y, w1, a.y));
        a.z = fmaf(v0.z, w0, fmaf(v1.z, w1, a.z));
        a.w = fmaf(v0.w, w0, fmaf(v1.w, w1, a.w));
    }
    if (e < end) {
        int s0 = g_csr_src[e];
        float w0 = g_dinv[s0];
        float4 v0 = *(const float4*)(X + (size_t)s0 * IN_DIM + c);
        a.x = fmaf(v0.x, w0, a.x);
        a.y = fmaf(v0.y, w0, a.y);
        a.z = fmaf(v0.z, w0, a.z);
        a.w = fmaf(v0.w, w0, a.w);
    }

    a.x *= wd; a.y *= wd; a.z *= wd; a.w *= wd;
    *(float4*)(g_aggx + (size_t)node * IN_DIM + c) = a;
}

// ---------------- unified 128x128 tiled GEMM body (device-side; pointers are
// device-resolved, so __device__ globals may be passed from wrapper kernels) ---
template <int KDIM, int NDIM, bool RELU, bool SCALE>
__device__ __forceinline__ void gemm_body(
    const float* __restrict__ A,
    const float* __restrict__ W,
    const float* __restrict__ bias_in,
    float* __restrict__ C)
{
    __shared__ float As[16][132];   // k-major, padded
    __shared__ float Bs[16][132];

    const int tid = threadIdx.x;
    const int bm  = blockIdx.x * 128;
    const int bn  = blockIdx.y * 128;
    const int tx  = tid & 15;       // 0..15 -> 8 cols each
    const int ty  = tid >> 4;       // 0..15 -> 8 rows each

    float acc[8][8] = {};
    float af[8], bf[8];

    for (int k0 = 0; k0 < KDIM; k0 += 16) {
        // A tile: 128 rows x 16 k = 512 float4, 2 per thread
        #pragma unroll
        for (int l = 0; l < 2; l++) {
            int f   = tid + l * 256;
            int row = f >> 2;
            int c4  = (f & 3) * 4;
            int gr  = bm + row;
            float4 v = make_float4(0.f, 0.f, 0.f, 0.f);
            if (gr < N_NODES) {
                v = *(const float4*)(A + (size_t)gr * KDIM + k0 + c4);
                if (RELU) {
                    float4 bb = *(const float4*)(bias_in + k0 + c4);
                    v.x = fmaxf(v.x + bb.x, 0.f);
                    v.y = fmaxf(v.y + bb.y, 0.f);
                    v.z = fmaxf(v.z + bb.z, 0.f);
                    v.w = fmaxf(v.w + bb.w, 0.f);
                }
            }
            As[c4 + 0][row] = v.x;
            As[c4 + 1][row] = v.y;
            As[c4 + 2][row] = v.z;
            As[c4 + 3][row] = v.w;
        }
        // B tile: 16 k x 128 n = 512 float4, 2 per thread
        #pragma unroll
        for (int l = 0; l < 2; l++) {
            int f   = tid + l * 256;
            int kr  = f >> 5;
            int col = (f & 31) * 4;
            float4 v = *(const float4*)(W + (size_t)(k0 + kr) * NDIM + bn + col);
            *(float4*)&Bs[kr][col] = v;
        }
        __syncthreads();

        #pragma unroll
        for (int k = 0; k < 16; k++) {
            *(float4*)&af[0] = *(const float4*)&As[k][ty * 8];
            *(float4*)&af[4] = *(const float4*)&As[k][ty * 8 + 4];
            *(float4*)&bf[0] = *(const float4*)&Bs[k][tx * 8];
            *(float4*)&bf[4] = *(const float4*)&Bs[k][tx * 8 + 4];
            #pragma unroll
            for (int i = 0; i < 8; i++)
                #pragma unroll
                for (int j = 0; j < 8; j++)
                    acc[i][j] = fmaf(af[i], bf[j], acc[i][j]);
        }
        __syncthreads();
    }

    #pragma unroll
    for (int i = 0; i < 8; i++) {
        int r = bm + ty * 8 + i;
        if (r >= N_NODES) break;
        float sc = SCALE ? g_dinv[r] : 1.0f;
        #pragma unroll
        for (int j = 0; j < 8; j += 4) {
            int cc = bn + tx * 8 + j;
            float4 o = make_float4(acc[i][j + 0] * sc, acc[i][j + 1] * sc,
                                   acc[i][j + 2] * sc, acc[i][j + 3] * sc);
            *(float4*)(C + (size_t)r * NDIM + cc) = o;
        }
    }
}

// wrappers: device globals referenced from DEVICE code (valid), only real
// harness pointers cross the host->device argument boundary.
__global__ void __launch_bounds__(256) gemm1_kernel(const float* __restrict__ W1)
{
    gemm_body<IN_DIM, HID_DIM, false, false>(g_aggx, W1, nullptr, g_h1);
}

__global__ void __launch_bounds__(256) gemm2_kernel(const float* __restrict__ W2,
                                                    const float* __restrict__ b1)
{
    gemm_body<HID_DIM, OUT_DIM, true, true>(g_h1, W2, b1, g_h2s);
}

// ---------------- agg2: out[d] = dinv[d]*(sum h2s[src] + h2s[d]) + b2 ----------------
__global__ void __launch_bounds__(256) agg2_kernel(
    const float* __restrict__ b2,
    float* __restrict__ out)
{
    int node = ((blockIdx.x * blockDim.x + threadIdx.x) >> 5);
    int lane = threadIdx.x & 31;
    if (node >= N_NODES) return;

    int beg = g_rowstart[node];
    int end = g_rowstart[node + 1];
    int c0 = lane * 4;

    float4 a0 = *(const float4*)(g_h2s + (size_t)node * OUT_DIM + c0);

    int e = beg;
    for (; e + 1 < end; e += 2) {
        int s0 = g_csr_src[e];
        int s1 = g_csr_src[e + 1];
        float4 v0 = *(const float4*)(g_h2s + (size_t)s0 * OUT_DIM + c0);
        float4 v1 = *(const float4*)(g_h2s + (size_t)s1 * OUT_DIM + c0);
        a0.x += v0.x + v1.x; a0.y += v0.y + v1.y;
        a0.z += v0.z + v1.z; a0.w += v0.w + v1.w;
    }
    if (e < end) {
        int s0 = g_csr_src[e];
        float4 v0 = *(const float4*)(g_h2s + (size_t)s0 * OUT_DIM + c0);
        a0.x += v0.x; a0.y += v0.y; a0.z += v0.z; a0.w += v0.w;
    }

    float w = g_dinv[node];
    float4 bb = *(const float4*)(b2 + c0);
    a0.x = a0.x * w + bb.x;
    a0.y = a0.y * w + bb.y;
    a0.z = a0.z * w + bb.z;
    a0.w = a0.w * w + bb.w;
    *(float4*)(out + (size_t)node * OUT_DIM + c0) = a0;
}

// ---------------- launch ----------------
extern "C" void kernel_launch(void* const* d_in, const int* in_sizes, int n_in,
                              void* d_out, int out_size)
{
    const float* x  = (const float*)d_in[0];
    const int*   ei = (const int*)d_in[1];
    const float* W1 = (const float*)d_in[2];
    const float* b1 = (const float*)d_in[3];
    const float* W2 = (const float*)d_in[4];
    const float* b2 = (const float*)d_in[5];
    float* out = (float*)d_out;

    // CSR build (by dst) + dinv
    detect_kernel<<<1, 1>>>(ei);
    zero_deg_kernel<<<(N_NODES + 255) / 256, 256>>>();
    convert_edges_kernel<<<(N_EDGES + 255) / 256, 256>>>(ei);
    block_sum_kernel<<<N_SCAN_BLOCKS, SCAN_BLK>>>();
    scan_blocksums_kernel<<<1, 256>>>();
    write_offsets_kernel<<<N_SCAN_BLOCKS, SCAN_BLK>>>();
    fill_csr_kernel<<<(N_EDGES + 255) / 256, 256>>>();

    // layer 1: aggregate-then-GEMM (linearity of GCN aggregation)
    aggx_kernel<<<(N_NODES + 7) / 8, 256>>>(x);
    dim3 g1((N_NODES + 127) / 128, HID_DIM / 128);
    gemm1_kernel<<<g1, 256>>>(W1);

    // layer 2: GEMM (fused relu(h1+b1) on A-load, *dinv epilogue) then aggregate
    dim3 g2((N_NODES + 127) / 128, OUT_DIM / 128);
    gemm2_kernel<<<g2, 256>>>(W2, b1);
    agg2_kernel<<<(N_NODES + 7) / 8, 256>>>(b2, out);
}

// round 9
// speedup vs baseline: 3.0805x; 1.0871x over previous
#include <cuda_runtime.h>
#include <math.h>

#define N_NODES 50000
#define N_EDGES 800000
#define IN_DIM  128
#define HID_DIM 256
#define OUT_DIM 128

#define SCAN_BLK 256
#define N_SCAN_BLOCKS ((N_NODES + SCAN_BLK - 1) / SCAN_BLK)   // 196

// ---------------- scratch (device globals: no allocs allowed) ----------------
__device__ int   g_is64;
__device__ int   g_deg     [N_NODES];
__device__ int   g_blocksum[N_SCAN_BLOCKS];
__device__ int   g_blockbase[N_SCAN_BLOCKS];
__device__ int   g_rowstart[N_NODES + 1];
__device__ int   g_cursor  [N_NODES];
__device__ int   g_csr_src [N_EDGES];
__device__ int   g_dst     [N_EDGES];
__device__ int   g_src     [N_EDGES];
__device__ float g_dinv    [N_NODES];
__device__ float g_aggx    [N_NODES * IN_DIM];    // normalized aggregation of x
__device__ float g_h1      [N_NODES * HID_DIM];   // aggx @ W1   (pre-bias/relu)
__device__ float g_h2s     [N_NODES * OUT_DIM];   // (relu(h1+b1)@W2) * dinv[row]

// ---------------- packed f32x2 helpers (sm_103a FFMA2 path) ----------------
__device__ __forceinline__ unsigned long long pack2(float lo, float hi) {
    unsigned long long r;
    asm("mov.b64 %0, {%1, %2};" : "=l"(r) : "f"(lo), "f"(hi));
    return r;
}
__device__ __forceinline__ void unpack2(unsigned long long v, float& lo, float& hi) {
    asm("mov.b64 {%0, %1}, %2;" : "=f"(lo), "=f"(hi) : "l"(v));
}
__device__ __forceinline__ void ffma2(unsigned long long& acc,
                                      unsigned long long a,
                                      unsigned long long b) {
    asm("fma.rn.f32x2 %0, %1, %2, %0;" : "+l"(acc) : "l"(a), "l"(b));
}

// ---------------- edge index dtype detection ----------------
__global__ void detect_kernel(const int* __restrict__ ei_raw) {
    int ornz = 0;
    #pragma unroll 8
    for (int i = 0; i < 512; i++) ornz |= ei_raw[2 * i + 1];
    g_is64 = (ornz == 0) ? 1 : 0;
}

__global__ void zero_deg_kernel() {
    int i = blockIdx.x * blockDim.x + threadIdx.x;
    if (i < N_NODES) g_deg[i] = 0;
}

__global__ void convert_edges_kernel(const int* __restrict__ ei_raw) {
    int e = blockIdx.x * blockDim.x + threadIdx.x;
    if (e >= N_EDGES) return;
    int s, d;
    if (g_is64) {
        const long long* p = (const long long*)ei_raw;
        s = (int)p[e];
        d = (int)p[N_EDGES + e];
    } else {
        s = ei_raw[e];
        d = ei_raw[N_EDGES + e];
    }
    g_src[e] = s;
    g_dst[e] = d;
    atomicAdd(&g_deg[d], 1);
}

// ---------------- parallel exclusive scan over g_deg ----------------
__global__ void __launch_bounds__(SCAN_BLK) block_sum_kernel() {
    __shared__ int sh[SCAN_BLK / 32];
    int i = blockIdx.x * SCAN_BLK + threadIdx.x;
    int v = (i < N_NODES) ? g_deg[i] : 0;
    #pragma unroll
    for (int o = 16; o > 0; o >>= 1) v += __shfl_down_sync(0xffffffffu, v, o);
    if ((threadIdx.x & 31) == 0) sh[threadIdx.x >> 5] = v;
    __syncthreads();
    if (threadIdx.x < SCAN_BLK / 32) {
        int w = sh[threadIdx.x];
        #pragma unroll
        for (int o = SCAN_BLK / 64; o > 0; o >>= 1) w += __shfl_down_sync(0xffu, w, o);
        if (threadIdx.x == 0) g_blocksum[blockIdx.x] = w;
    }
}

__global__ void __launch_bounds__(256) scan_blocksums_kernel() {
    __shared__ int sh[256];
    int tid = threadIdx.x;
    int v = (tid < N_SCAN_BLOCKS) ? g_blocksum[tid] : 0;
    sh[tid] = v;
    __syncthreads();
    for (int ofs = 1; ofs < 256; ofs <<= 1) {
        int u = (tid >= ofs) ? sh[tid - ofs] : 0;
        __syncthreads();
        sh[tid] += u;
        __syncthreads();
    }
    if (tid < N_SCAN_BLOCKS) g_blockbase[tid] = sh[tid] - v;
    if (tid == N_SCAN_BLOCKS - 1) g_rowstart[N_NODES] = sh[tid];
}

__global__ void __launch_bounds__(SCAN_BLK) write_offsets_kernel() {
    __shared__ int sh[SCAN_BLK];
    int tid = threadIdx.x;
    int i = blockIdx.x * SCAN_BLK + tid;
    int d = (i < N_NODES) ? g_deg[i] : 0;
    sh[tid] = d;
    __syncthreads();
    for (int ofs = 1; ofs < SCAN_BLK; ofs <<= 1) {
        int u = (tid >= ofs) ? sh[tid - ofs] : 0;
        __syncthreads();
        sh[tid] += u;
        __syncthreads();
    }
    if (i < N_NODES) {
        int start = g_blockbase[blockIdx.x] + sh[tid] - d;
        g_rowstart[i] = start;
        g_cursor[i]   = start;
        g_dinv[i]     = rsqrtf((float)d + 1.0f);
    }
}

__global__ void fill_csr_kernel() {
    int e = blockIdx.x * blockDim.x + threadIdx.x;
    if (e >= N_EDGES) return;
    int pos = atomicAdd(&g_cursor[g_dst[e]], 1);
    g_csr_src[pos] = g_src[e];
}

// ---------------- aggX: g_aggx[d] = dinv[d]*(sum dinv[s]*x[s] + dinv[d]*x[d]) ----------------
__global__ void __launch_bounds__(256) aggx_kernel(const float* __restrict__ X)
{
    int node = ((blockIdx.x * blockDim.x + threadIdx.x) >> 5);
    int lane = threadIdx.x & 31;
    if (node >= N_NODES) return;

    int beg = g_rowstart[node];
    int end = g_rowstart[node + 1];
    int c = lane * 4;

    float wd = g_dinv[node];
    float4 v = *(const float4*)(X + (size_t)node * IN_DIM + c);
    float4 a = make_float4(v.x * wd, v.y * wd, v.z * wd, v.w * wd);

    int e = beg;
    for (; e + 1 < end; e += 2) {
        int s0 = g_csr_src[e];
        int s1 = g_csr_src[e + 1];
        float w0 = g_dinv[s0];
        float w1 = g_dinv[s1];
        float4 v0 = *(const float4*)(X + (size_t)s0 * IN_DIM + c);
        float4 v1 = *(const float4*)(X + (size_t)s1 * IN_DIM + c);
        a.x = fmaf(v0.x, w0, fmaf(v1.x, w1, a.x));
        a.y = fmaf(v0.y, w0, fmaf(v1.y, w1, a.y));
        a.z = fmaf(v0.z, w0, fmaf(v1.z, w1, a.z));
        a.w = fmaf(v0.w, w0, fmaf(v1.w, w1, a.w));
    }
    if (e < end) {
        int s0 = g_csr_src[e];
        float w0 = g_dinv[s0];
        float4 v0 = *(const float4*)(X + (size_t)s0 * IN_DIM + c);
        a.x = fmaf(v0.x, w0, a.x);
        a.y = fmaf(v0.y, w0, a.y);
        a.z = fmaf(v0.z, w0, a.z);
        a.w = fmaf(v0.w, w0, a.w);
    }

    a.x *= wd; a.y *= wd; a.z *= wd; a.w *= wd;
    *(float4*)(g_aggx + (size_t)node * IN_DIM + c) = a;
}

// ---------------- unified 128x128 tiled GEMM body, FFMA2 microkernel ----------------
// C[M,NDIM] = op(A)[M,KDIM] @ W[KDIM,NDIM];  op = relu(.+bias) if RELU
// epilogue: *dinv[row] if SCALE. Register-staged prefetch of next K-chunk.
template <int KDIM, int NDIM, bool RELU, bool SCALE>
__device__ __forceinline__ void gemm_body(
    const float* __restrict__ A,
    const float* __restrict__ W,
    const float* __restrict__ bias_in,
    float* __restrict__ C)
{
    __shared__ float As[16][132];   // k-major, padded
    __shared__ float Bs[16][132];

    const int tid = threadIdx.x;
    const int bm  = blockIdx.x * 128;
    const int bn  = blockIdx.y * 128;
    const int tx  = tid & 15;       // 8 cols each
    const int ty  = tid >> 4;       // 8 rows each

    // load mapping (2 float4 per thread per tile)
    const int a_row0 = tid >> 2;            // f = tid
    const int a_c40  = (tid & 3) * 4;
    const int b_k0   = tid >> 5;
    const int b_col0 = (tid & 31) * 4;

    unsigned long long acc2[8][4];
    #pragma unroll
    for (int i = 0; i < 8; i++)
        #pragma unroll
        for (int j = 0; j < 4; j++) acc2[i][j] = 0ULL;

    float4 a_reg[2], b_reg[2];

    auto load_tiles = [&](int k0) {
        #pragma unroll
        for (int l = 0; l < 2; l++) {
            int row = a_row0 + l * 64;
            int gr  = bm + row;
            float4 v = make_float4(0.f, 0.f, 0.f, 0.f);
            if (gr < N_NODES) {
                v = *(const float4*)(A + (size_t)gr * KDIM + k0 + a_c40);
                if (RELU) {
                    float4 bb = *(const float4*)(bias_in + k0 + a_c40);
                    v.x = fmaxf(v.x + bb.x, 0.f);
                    v.y = fmaxf(v.y + bb.y, 0.f);
                    v.z = fmaxf(v.z + bb.z, 0.f);
                    v.w = fmaxf(v.w + bb.w, 0.f);
                }
            }
            a_reg[l] = v;
        }
        #pragma unroll
        for (int l = 0; l < 2; l++) {
            int kr = b_k0 + l * 8;
            b_reg[l] = *(const float4*)(W + (size_t)(k0 + kr) * NDIM + bn + b_col0);
        }
    };

    auto store_tiles = [&]() {
        #pragma unroll
        for (int l = 0; l < 2; l++) {
            int row = a_row0 + l * 64;
            As[a_c40 + 0][row] = a_reg[l].x;
            As[a_c40 + 1][row] = a_reg[l].y;
            As[a_c40 + 2][row] = a_reg[l].z;
            As[a_c40 + 3][row] = a_reg[l].w;
        }
        #pragma unroll
        for (int l = 0; l < 2; l++) {
            int kr = b_k0 + l * 8;
            *(float4*)&Bs[kr][b_col0] = b_reg[l];
        }
    };

    load_tiles(0);

    for (int k0 = 0; k0 < KDIM; k0 += 16) {
        store_tiles();
        __syncthreads();

        if (k0 + 16 < KDIM) load_tiles(k0 + 16);   // prefetch next chunk

        float af[8], bf[8];
        #pragma unroll
        for (int k = 0; k < 16; k++) {
            *(float4*)&af[0] = *(const float4*)&As[k][ty * 8];
            *(float4*)&af[4] = *(const float4*)&As[k][ty * 8 + 4];
            *(float4*)&bf[0] = *(const float4*)&Bs[k][tx * 8];
            *(float4*)&bf[4] = *(const float4*)&Bs[k][tx * 8 + 4];

            unsigned long long bp[4];
            bp[0] = pack2(bf[0], bf[1]);
            bp[1] = pack2(bf[2], bf[3]);
            bp[2] = pack2(bf[4], bf[5]);
            bp[3] = pack2(bf[6], bf[7]);

            #pragma unroll
            for (int i = 0; i < 8; i++) {
                unsigned long long ap = pack2(af[i], af[i]);
                ffma2(acc2[i][0], ap, bp[0]);
                ffma2(acc2[i][1], ap, bp[1]);
                ffma2(acc2[i][2], ap, bp[2]);
                ffma2(acc2[i][3], ap, bp[3]);
            }
        }
        __syncthreads();
    }

    #pragma unroll
    for (int i = 0; i < 8; i++) {
        int r = bm + ty * 8 + i;
        if (r >= N_NODES) break;
        float sc = SCALE ? g_dinv[r] : 1.0f;
        float o[8];
        #pragma unroll
        for (int j = 0; j < 4; j++) unpack2(acc2[i][j], o[2 * j], o[2 * j + 1]);
        #pragma unroll
        for (int j = 0; j < 8; j += 4) {
            int cc = bn + tx * 8 + j;
            float4 ov = make_float4(o[j] * sc, o[j + 1] * sc,
                                    o[j + 2] * sc, o[j + 3] * sc);
            *(float4*)(C + (size_t)r * NDIM + cc) = ov;
        }
    }
}

// wrappers: device globals referenced from DEVICE code only.
__global__ void __launch_bounds__(256) gemm1_kernel(const float* __restrict__ W1)
{
    gemm_body<IN_DIM, HID_DIM, false, false>(g_aggx, W1, nullptr, g_h1);
}

__global__ void __launch_bounds__(256) gemm2_kernel(const float* __restrict__ W2,
                                                    const float* __restrict__ b1)
{
    gemm_body<HID_DIM, OUT_DIM, true, true>(g_h1, W2, b1, g_h2s);
}

// ---------------- agg2: out[d] = dinv[d]*(sum h2s[src] + h2s[d]) + b2 ----------------
__global__ void __launch_bounds__(256) agg2_kernel(
    const float* __restrict__ b2,
    float* __restrict__ out)
{
    int node = ((blockIdx.x * blockDim.x + threadIdx.x) >> 5);
    int lane = threadIdx.x & 31;
    if (node >= N_NODES) return;

    int beg = g_rowstart[node];
    int end = g_rowstart[node + 1];
    int c0 = lane * 4;

    float4 a0 = *(const float4*)(g_h2s + (size_t)node * OUT_DIM + c0);

    int e = beg;
    for (; e + 1 < end; e += 2) {
        int s0 = g_csr_src[e];
        int s1 = g_csr_src[e + 1];
        float4 v0 = *(const float4*)(g_h2s + (size_t)s0 * OUT_DIM + c0);
        float4 v1 = *(const float4*)(g_h2s + (size_t)s1 * OUT_DIM + c0);
        a0.x += v0.x + v1.x; a0.y += v0.y + v1.y;
        a0.z += v0.z + v1.z; a0.w += v0.w + v1.w;
    }
    if (e < end) {
        int s0 = g_csr_src[e];
        float4 v0 = *(const float4*)(g_h2s + (size_t)s0 * OUT_DIM + c0);
        a0.x += v0.x; a0.y += v0.y; a0.z += v0.z; a0.w += v0.w;
    }

    float w = g_dinv[node];
    float4 bb = *(const float4*)(b2 + c0);
    a0.x = a0.x * w + bb.x;
    a0.y = a0.y * w + bb.y;
    a0.z = a0.z * w + bb.z;
    a0.w = a0.w * w + bb.w;
    *(float4*)(out + (size_t)node * OUT_DIM + c0) = a0;
}

// ---------------- launch ----------------
extern "C" void kernel_launch(void* const* d_in, const int* in_sizes, int n_in,
                              void* d_out, int out_size)
{
    const float* x  = (const float*)d_in[0];
    const int*   ei = (const int*)d_in[1];
    const float* W1 = (const float*)d_in[2];
    const float* b1 = (const float*)d_in[3];
    const float* W2 = (const float*)d_in[4];
    const float* b2 = (const float*)d_in[5];
    float* out = (float*)d_out;

    // CSR build (by dst) + dinv
    detect_kernel<<<1, 1>>>(ei);
    zero_deg_kernel<<<(N_NODES + 255) / 256, 256>>>();
    convert_edges_kernel<<<(N_EDGES + 255) / 256, 256>>>(ei);
    block_sum_kernel<<<N_SCAN_BLOCKS, SCAN_BLK>>>();
    scan_blocksums_kernel<<<1, 256>>>();
    write_offsets_kernel<<<N_SCAN_BLOCKS, SCAN_BLK>>>();
    fill_csr_kernel<<<(N_EDGES + 255) / 256, 256>>>();

    // layer 1: aggregate-then-GEMM (linearity of GCN aggregation)
    aggx_kernel<<<(N_NODES + 7) / 8, 256>>>(x);
    dim3 g1((N_NODES + 127) / 128, HID_DIM / 128);
    gemm1_kernel<<<g1, 256>>>(W1);

    // layer 2: GEMM (fused relu(h1+b1) on A-load, *dinv epilogue) then aggregate
    dim3 g2((N_NODES + 127) / 128, OUT_DIM / 128);
    gemm2_kernel<<<g2, 256>>>(W2, b1);
    agg2_kernel<<<(N_NODES + 7) / 8, 256>>>(b2, out);
}

// round 14
// speedup vs baseline: 4.0990x; 1.3307x over previous
#include <cuda_runtime.h>
#include <cuda_bf16.h>
#include <math.h>

typedef unsigned int       u32;
typedef unsigned long long u64;

#define N_NODES 50000
#define N_EDGES 800000
#define IN_DIM  128
#define HID_DIM 256
#define OUT_DIM 128

#define SCAN_BLK 256
#define N_SCAN_BLOCKS ((N_NODES + SCAN_BLK - 1) / SCAN_BLK)   // 196
#define N_TILES ((N_NODES + 127) / 128)                        // 391
#define M_PAD   (N_TILES * 128)                                // 50048

// ---------------- scratch (device globals: no allocs allowed) ----------------
__device__ int   g_is64;
__device__ int   g_deg     [N_NODES];
__device__ int   g_blocksum[N_SCAN_BLOCKS];
__device__ int   g_blockbase[N_SCAN_BLOCKS];
__device__ int   g_rowstart[N_NODES + 1];
__device__ int   g_cursor  [N_NODES];
__device__ int   g_csr_src [N_EDGES];
__device__ int   g_dst     [N_EDGES];
__device__ int   g_src     [N_EDGES];
__device__ float g_dinv    [N_NODES];
// split-bf16 operands (pad rows of g_a1_* stay zero; never written)
__device__ __nv_bfloat16 g_a1_hi[M_PAD * IN_DIM];
__device__ __nv_bfloat16 g_a1_lo[M_PAD * IN_DIM];
__device__ __nv_bfloat16 g_h1_hi[M_PAD * HID_DIM];
__device__ __nv_bfloat16 g_h1_lo[M_PAD * HID_DIM];
__device__ float g_h2s[M_PAD * OUT_DIM];
// W transposed [N][K] + bf16-split
__device__ __nv_bfloat16 g_w1t_hi[HID_DIM * IN_DIM];
__device__ __nv_bfloat16 g_w1t_lo[HID_DIM * IN_DIM];
__device__ __nv_bfloat16 g_w2t_hi[OUT_DIM * HID_DIM];
__device__ __nv_bfloat16 g_w2t_lo[OUT_DIM * HID_DIM];

// ---------------- helpers ----------------
__device__ __forceinline__ u32 smem_u32(const void* p) {
    u32 a;
    asm("{ .reg .u64 t; cvta.to.shared.u64 t, %1; cvt.u32.u64 %0, t; }" : "=r"(a) : "l"(p));
    return a;
}
__device__ __forceinline__ u32 pack_bf16x2(__nv_bfloat16 a, __nv_bfloat16 b) {
    u32 lo = (u32)__bfloat16_as_ushort(a);
    u32 hi = (u32)__bfloat16_as_ushort(b);
    return lo | (hi << 16);
}
__device__ __forceinline__ void split_f32(float v, __nv_bfloat16& hi, __nv_bfloat16& lo) {
    hi = __float2bfloat16(v);
    lo = __float2bfloat16(v - __bfloat162float(hi));
}
__device__ __forceinline__ void ldsm_x4(u32& r0, u32& r1, u32& r2, u32& r3, u32 addr) {
    asm volatile("ldmatrix.sync.aligned.m8n8.x4.shared.b16 {%0,%1,%2,%3}, [%4];"
                 : "=r"(r0), "=r"(r1), "=r"(r2), "=r"(r3) : "r"(addr));
}
__device__ __forceinline__ void mma_bf16(float& d0, float& d1, float& d2, float& d3,
                                         u32 a0, u32 a1, u32 a2, u32 a3, u32 b0, u32 b1) {
    asm volatile(
        "mma.sync.aligned.m16n8k16.row.col.f32.bf16.bf16.f32 "
        "{%0,%1,%2,%3}, {%4,%5,%6,%7}, {%8,%9}, {%0,%1,%2,%3};"
        : "+f"(d0), "+f"(d1), "+f"(d2), "+f"(d3)
        : "r"(a0), "r"(a1), "r"(a2), "r"(a3), "r"(b0), "r"(b1));
}

// ---------------- edge index dtype detection ----------------
__global__ void detect_kernel(const int* __restrict__ ei_raw) {
    int ornz = 0;
    #pragma unroll 8
    for (int i = 0; i < 512; i++) ornz |= ei_raw[2 * i + 1];
    g_is64 = (ornz == 0) ? 1 : 0;
}

__global__ void zero_deg_kernel() {
    int i = blockIdx.x * blockDim.x + threadIdx.x;
    if (i < N_NODES) g_deg[i] = 0;
}

__global__ void convert_edges_kernel(const int* __restrict__ ei_raw) {
    int e = blockIdx.x * blockDim.x + threadIdx.x;
    if (e >= N_EDGES) return;
    int s, d;
    if (g_is64) {
        const long long* p = (const long long*)ei_raw;
        s = (int)p[e];
        d = (int)p[N_EDGES + e];
    } else {
        s = ei_raw[e];
        d = ei_raw[N_EDGES + e];
    }
    g_src[e] = s;
    g_dst[e] = d;
    atomicAdd(&g_deg[d], 1);
}

// W1 [128,256] -> g_w1t [256][128]; W2 [256,128] -> g_w2t [128][256]
__global__ void convert_w1_kernel(const float* __restrict__ W1) {
    int i = blockIdx.x * blockDim.x + threadIdx.x;
    if (i >= IN_DIM * HID_DIM) return;
    int k = i / HID_DIM;
    int n = i % HID_DIM;
    __nv_bfloat16 hi, lo;
    split_f32(W1[i], hi, lo);
    g_w1t_hi[n * IN_DIM + k] = hi;
    g_w1t_lo[n * IN_DIM + k] = lo;
}
__global__ void convert_w2_kernel(const float* __restrict__ W2) {
    int i = blockIdx.x * blockDim.x + threadIdx.x;
    if (i >= HID_DIM * OUT_DIM) return;
    int k = i / OUT_DIM;
    int n = i % OUT_DIM;
    __nv_bfloat16 hi, lo;
    split_f32(W2[i], hi, lo);
    g_w2t_hi[n * HID_DIM + k] = hi;
    g_w2t_lo[n * HID_DIM + k] = lo;
}

// ---------------- parallel exclusive scan over g_deg ----------------
__global__ void __launch_bounds__(SCAN_BLK) block_sum_kernel() {
    __shared__ int sh[SCAN_BLK / 32];
    int i = blockIdx.x * SCAN_BLK + threadIdx.x;
    int v = (i < N_NODES) ? g_deg[i] : 0;
    #pragma unroll
    for (int o = 16; o > 0; o >>= 1) v += __shfl_down_sync(0xffffffffu, v, o);
    if ((threadIdx.x & 31) == 0) sh[threadIdx.x >> 5] = v;
    __syncthreads();
    if (threadIdx.x < SCAN_BLK / 32) {
        int w = sh[threadIdx.x];
        #pragma unroll
        for (int o = SCAN_BLK / 64; o > 0; o >>= 1) w += __shfl_down_sync(0xffu, w, o);
        if (threadIdx.x == 0) g_blocksum[blockIdx.x] = w;
    }
}

__global__ void __launch_bounds__(256) scan_blocksums_kernel() {
    __shared__ int sh[256];
    int tid = threadIdx.x;
    int v = (tid < N_SCAN_BLOCKS) ? g_blocksum[tid] : 0;
    sh[tid] = v;
    __syncthreads();
    for (int ofs = 1; ofs < 256; ofs <<= 1) {
        int u = (tid >= ofs) ? sh[tid - ofs] : 0;
        __syncthreads();
        sh[tid] += u;
        __syncthreads();
    }
    if (tid < N_SCAN_BLOCKS) g_blockbase[tid] = sh[tid] - v;
    if (tid == N_SCAN_BLOCKS - 1) g_rowstart[N_NODES] = sh[tid];
}

__global__ void __launch_bounds__(SCAN_BLK) write_offsets_kernel() {
    __shared__ int sh[SCAN_BLK];
    int tid = threadIdx.x;
    int i = blockIdx.x * SCAN_BLK + tid;
    int d = (i < N_NODES) ? g_deg[i] : 0;
    sh[tid] = d;
    __syncthreads();
    for (int ofs = 1; ofs < SCAN_BLK; ofs <<= 1) {
        int u = (tid >= ofs) ? sh[tid - ofs] : 0;
        __syncthreads();
        sh[tid] += u;
        __syncthreads();
    }
    if (i < N_NODES) {
        int start = g_blockbase[blockIdx.x] + sh[tid] - d;
        g_rowstart[i] = start;
        g_cursor[i]   = start;
        g_dinv[i]     = rsqrtf((float)d + 1.0f);
    }
}

__global__ void fill_csr_kernel() {
    int e = blockIdx.x * blockDim.x + threadIdx.x;
    if (e >= N_EDGES) return;
    int pos = atomicAdd(&g_cursor[g_dst[e]], 1);
    g_csr_src[pos] = g_src[e];
}

// ---------------- aggX: split-bf16 out of dinv[d]*(sum dinv[s]*x[s] + dinv[d]*x[d]) ----------------
__global__ void __launch_bounds__(256) aggx_kernel(const float* __restrict__ X)
{
    int node = ((blockIdx.x * blockDim.x + threadIdx.x) >> 5);
    int lane = threadIdx.x & 31;
    if (node >= N_NODES) return;

    int beg = g_rowstart[node];
    int end = g_rowstart[node + 1];
    int c = lane * 4;

    float wd = g_dinv[node];
    float4 v = *(const float4*)(X + (size_t)node * IN_DIM + c);
    float4 a = make_float4(v.x * wd, v.y * wd, v.z * wd, v.w * wd);

    int e = beg;
    for (; e + 1 < end; e += 2) {
        int s0 = g_csr_src[e];
        int s1 = g_csr_src[e + 1];
        float w0 = g_dinv[s0];
        float w1 = g_dinv[s1];
        float4 v0 = *(const float4*)(X + (size_t)s0 * IN_DIM + c);
        float4 v1 = *(const float4*)(X + (size_t)s1 * IN_DIM + c);
        a.x = fmaf(v0.x, w0, fmaf(v1.x, w1, a.x));
        a.y = fmaf(v0.y, w0, fmaf(v1.y, w1, a.y));
        a.z = fmaf(v0.z, w0, fmaf(v1.z, w1, a.z));
        a.w = fmaf(v0.w, w0, fmaf(v1.w, w1, a.w));
    }
    if (e < end) {
        int s0 = g_csr_src[e];
        float w0 = g_dinv[s0];
        float4 v0 = *(const float4*)(X + (size_t)s0 * IN_DIM + c);
        a.x = fmaf(v0.x, w0, a.x);
        a.y = fmaf(v0.y, w0, a.y);
        a.z = fmaf(v0.z, w0, a.z);
        a.w = fmaf(v0.w, w0, a.w);
    }

    a.x *= wd; a.y *= wd; a.z *= wd; a.w *= wd;

    __nv_bfloat16 h0, l0, h1, l1, h2, l2, h3, l3;
    split_f32(a.x, h0, l0);
    split_f32(a.y, h1, l1);
    split_f32(a.z, h2, l2);
    split_f32(a.w, h3, l3);
    uint2 hv, lv;
    hv.x = pack_bf16x2(h0, h1); hv.y = pack_bf16x2(h2, h3);
    lv.x = pack_bf16x2(l0, l1); lv.y = pack_bf16x2(l2, l3);
    *(uint2*)(g_a1_hi + (size_t)node * IN_DIM + c) = hv;
    *(uint2*)(g_a1_lo + (size_t)node * IN_DIM + c) = lv;
}

// ---------------- mma.sync split-bf16 GEMM ----------------
// C[M,NDIM] = A[M,KDIM] @ Wt[NDIM,KDIM]^T  (3-term split accumulation)
// SPLIT_OUT: C' = relu(C + bias) split-> (Chi, Clo) bf16
// else:      Cf = C * dinv[row]
template <int KDIM, int NDIM, bool SPLIT_OUT>
__device__ __forceinline__ void mma_gemm_body(
    const __nv_bfloat16* __restrict__ Ahi, const __nv_bfloat16* __restrict__ Alo,
    const __nv_bfloat16* __restrict__ Whi, const __nv_bfloat16* __restrict__ Wlo,
    const float* __restrict__ bias,
    __nv_bfloat16* __restrict__ Chi, __nv_bfloat16* __restrict__ Clo,
    float* __restrict__ Cf)
{
    // pitch 40 bf16 (80B): ldmatrix conflict-free, 16B-aligned rows
    __shared__ __nv_bfloat16 sAh[128][40];
    __shared__ __nv_bfloat16 sAl[128][40];
    __shared__ __nv_bfloat16 sBh[128][40];
    __shared__ __nv_bfloat16 sBl[128][40];

    const int tid    = threadIdx.x;      // 256 threads
    const int lane   = tid & 31;
    const int warp   = tid >> 5;         // 0..7
    const int warp_m = warp & 3;         // 4 m-rows of 32
    const int warp_n = warp >> 2;        // 2 n-cols of 64
    const int bm     = blockIdx.x * 128;
    const int bn     = blockIdx.y * 128;

    float acc[2][8][4];
    #pragma unroll
    for (int i = 0; i < 2; i++)
        #pragma unroll
        for (int j = 0; j < 8; j++)
            #pragma unroll
            for (int q = 0; q < 4; q++) acc[i][j][q] = 0.f;

    const u32 sAh_b = smem_u32(sAh);
    const u32 sAl_b = smem_u32(sAl);
    const u32 sBh_b = smem_u32(sBh);
    const u32 sBl_b = smem_u32(sBl);

    // frag address components (constant across chunks)
    const int a_lr = lane & 15;
    const int a_ko = (lane < 16) ? 0 : 8;
    const int b_l8 = lane & 7;
    const int b_gr = lane >> 3;
    const int b_nrow = (b_gr & 2) ? (b_l8 + 8) : b_l8;
    const int b_ko   = (b_gr & 1) ? 8 : 0;

    for (int kc = 0; kc < KDIM / 32; kc++) {
        // ---- stage 32-wide K chunk of A(hi,lo) and B(hi,lo) ----
        #pragma unroll
        for (int l = 0; l < 2; l++) {
            int idx = tid + l * 256;      // 0..511
            int row = idx >> 2;           // 0..127
            int c4  = idx & 3;            // float4 (8 bf16) within 32
            size_t ga = (size_t)(bm + row) * KDIM + kc * 32 + c4 * 8;
            size_t gb = (size_t)(bn + row) * KDIM + kc * 32 + c4 * 8;
            *(float4*)(&sAh[row][c4 * 8]) = *(const float4*)(Ahi + ga);
            *(float4*)(&sAl[row][c4 * 8]) = *(const float4*)(Alo + ga);
            *(float4*)(&sBh[row][c4 * 8]) = *(const float4*)(Whi + gb);
            *(float4*)(&sBl[row][c4 * 8]) = *(const float4*)(Wlo + gb);
        }
        __syncthreads();

        #pragma unroll
        for (int ks = 0; ks < 32; ks += 16) {
            u32 ah[2][4], al[2][4];
            #pragma unroll
            for (int mt = 0; mt < 2; mt++) {
                u32 off = (u32)((warp_m * 32 + mt * 16 + a_lr) * 40 + ks + a_ko) * 2;
                ldsm_x4(ah[mt][0], ah[mt][1], ah[mt][2], ah[mt][3], sAh_b + off);
                ldsm_x4(al[mt][0], al[mt][1], al[mt][2], al[mt][3], sAl_b + off);
            }
            u32 bh[8][2], bl[8][2];
            #pragma unroll
            for (int ntp = 0; ntp < 4; ntp++) {
                u32 off = (u32)((warp_n * 64 + ntp * 16 + b_nrow) * 40 + ks + b_ko) * 2;
                ldsm_x4(bh[2 * ntp][0], bh[2 * ntp][1], bh[2 * ntp + 1][0], bh[2 * ntp + 1][1], sBh_b + off);
                ldsm_x4(bl[2 * ntp][0], bl[2 * ntp][1], bl[2 * ntp + 1][0], bl[2 * ntp + 1][1], sBl_b + off);
            }
            #pragma unroll
            for (int mt = 0; mt < 2; mt++) {
                #pragma unroll
                for (int nt = 0; nt < 8; nt++) {
                    float* d = acc[mt][nt];
                    mma_bf16(d[0], d[1], d[2], d[3],
                             ah[mt][0], ah[mt][1], ah[mt][2], ah[mt][3],
                             bh[nt][0], bh[nt][1]);
                    mma_bf16(d[0], d[1], d[2], d[3],
                             ah[mt][0], ah[mt][1], ah[mt][2], ah[mt][3],
                             bl[nt][0], bl[nt][1]);
                    mma_bf16(d[0], d[1], d[2], d[3],
                             al[mt][0], al[mt][1], al[mt][2], al[mt][3],
                             bh[nt][0], bh[nt][1]);
                }
            }
        }
        __syncthreads();
    }

    // ---- epilogue ----
    const int g   = lane >> 2;
    const int tig = lane & 3;
    #pragma unroll
    for (int mt = 0; mt < 2; mt++) {
        int r0 = bm + warp_m * 32 + mt * 16 + g;
        int r1 = r0 + 8;
        #pragma unroll
        for (int nt = 0; nt < 8; nt++) {
            int col = bn + warp_n * 64 + nt * 8 + tig * 2;
            float c0 = acc[mt][nt][0];
            float c1 = acc[mt][nt][1];
            float c2 = acc[mt][nt][2];
            float c3 = acc[mt][nt][3];
            if (SPLIT_OUT) {
                float bb0 = bias[col];
                float bb1 = bias[col + 1];
                float v0 = fmaxf(c0 + bb0, 0.f);
                float v1 = fmaxf(c1 + bb1, 0.f);
                float v2 = fmaxf(c2 + bb0, 0.f);
                float v3 = fmaxf(c3 + bb1, 0.f);
                __nv_bfloat16 h0, l0, h1, l1;
                split_f32(v0, h0, l0);
                split_f32(v1, h1, l1);
                *(u32*)(Chi + (size_t)r0 * NDIM + col) = pack_bf16x2(h0, h1);
                *(u32*)(Clo + (size_t)r0 * NDIM + col) = pack_bf16x2(l0, l1);
                split_f32(v2, h0, l0);
                split_f32(v3, h1, l1);
                *(u32*)(Chi + (size_t)r1 * NDIM + col) = pack_bf16x2(h0, h1);
                *(u32*)(Clo + (size_t)r1 * NDIM + col) = pack_bf16x2(l0, l1);
            } else {
                float s0 = (r0 < N_NODES) ? g_dinv[r0] : 0.f;
                float s1 = (r1 < N_NODES) ? g_dinv[r1] : 0.f;
                float2 o0 = make_float2(c0 * s0, c1 * s0);
                float2 o1 = make_float2(c2 * s1, c3 * s1);
                *(float2*)(Cf + (size_t)r0 * NDIM + col) = o0;
                *(float2*)(Cf + (size_t)r1 * NDIM + col) = o1;
            }
        }
    }
}

__global__ void __launch_bounds__(256) mma_gemm1_kernel(const float* __restrict__ b1)
{
    mma_gemm_body<IN_DIM, HID_DIM, true>(g_a1_hi, g_a1_lo, g_w1t_hi, g_w1t_lo,
                                         b1, g_h1_hi, g_h1_lo, (float*)0);
}

__global__ void __launch_bounds__(256) mma_gemm2_kernel()
{
    mma_gemm_body<HID_DIM, OUT_DIM, false>(g_h1_hi, g_h1_lo, g_w2t_hi, g_w2t_lo,
                                           (const float*)0, (__nv_bfloat16*)0, (__nv_bfloat16*)0, g_h2s);
}

// ---------------- agg2: out[d] = dinv[d]*(sum h2s[src] + h2s[d]) + b2 ----------------
__global__ void __launch_bounds__(256) agg2_kernel(
    const float* __restrict__ b2,
    float* __restrict__ out)
{
    int node = ((blockIdx.x * blockDim.x + threadIdx.x) >> 5);
    int lane = threadIdx.x & 31;
    if (node >= N_NODES) return;

    int beg = g_rowstart[node];
    int end = g_rowstart[node + 1];
    int c0 = lane * 4;

    float4 a0 = *(const float4*)(g_h2s + (size_t)node * OUT_DIM + c0);

    int e = beg;
    for (; e + 1 < end; e += 2) {
        int s0 = g_csr_src[e];
        int s1 = g_csr_src[e + 1];
        float4 v0 = *(const float4*)(g_h2s + (size_t)s0 * OUT_DIM + c0);
        float4 v1 = *(const float4*)(g_h2s + (size_t)s1 * OUT_DIM + c0);
        a0.x += v0.x + v1.x; a0.y += v0.y + v1.y;
        a0.z += v0.z + v1.z; a0.w += v0.w + v1.w;
    }
    if (e < end) {
        int s0 = g_csr_src[e];
        float4 v0 = *(const float4*)(g_h2s + (size_t)s0 * OUT_DIM + c0);
        a0.x += v0.x; a0.y += v0.y; a0.z += v0.z; a0.w += v0.w;
    }

    float w = g_dinv[node];
    float4 bb = *(const float4*)(b2 + c0);
    a0.x = a0.x * w + bb.x;
    a0.y = a0.y * w + bb.y;
    a0.z = a0.z * w + bb.z;
    a0.w = a0.w * w + bb.w;
    *(float4*)(out + (size_t)node * OUT_DIM + c0) = a0;
}

// ---------------- launch ----------------
extern "C" void kernel_launch(void* const* d_in, const int* in_sizes, int n_in,
                              void* d_out, int out_size)
{
    const float* x  = (const float*)d_in[0];
    const int*   ei = (const int*)d_in[1];
    const float* W1 = (const float*)d_in[2];
    const float* b1 = (const float*)d_in[3];
    const float* W2 = (const float*)d_in[4];
    const float* b2 = (const float*)d_in[5];
    float* out = (float*)d_out;

    // CSR build (by dst) + dinv + weight conversion
    detect_kernel<<<1, 1>>>(ei);
    zero_deg_kernel<<<(N_NODES + 255) / 256, 256>>>();
    convert_edges_kernel<<<(N_EDGES + 255) / 256, 256>>>(ei);
    convert_w1_kernel<<<(IN_DIM * HID_DIM + 255) / 256, 256>>>(W1);
    convert_w2_kernel<<<(HID_DIM * OUT_DIM + 255) / 256, 256>>>(W2);
    block_sum_kernel<<<N_SCAN_BLOCKS, SCAN_BLK>>>();
    scan_blocksums_kernel<<<1, 256>>>();
    write_offsets_kernel<<<N_SCAN_BLOCKS, SCAN_BLK>>>();
    fill_csr_kernel<<<(N_EDGES + 255) / 256, 256>>>();

    // layer 1: aggregate (split-bf16 out) then HMMA GEMM (fused relu+b1, split-bf16 out)
    aggx_kernel<<<(N_NODES + 7) / 8, 256>>>(x);
    {
        dim3 grid(N_TILES, HID_DIM / 128);
        mma_gemm1_kernel<<<grid, 256>>>(b1);
    }

    // layer 2: HMMA GEMM (*dinv epilogue) then aggregate
    {
        dim3 grid(N_TILES, OUT_DIM / 128);
        mma_gemm2_kernel<<<grid, 256>>>();
    }
    agg2_kernel<<<(N_NODES + 7) / 8, 256>>>(b2, out);
}

// round 15
// speedup vs baseline: 4.9431x; 1.2059x over previous
#include <cuda_runtime.h>
#include <cuda_bf16.h>
#include <math.h>

typedef unsigned int       u32;
typedef unsigned long long u64;

#define N_NODES 50000
#define N_EDGES 800000
#define IN_DIM  128
#define HID_DIM 256
#define OUT_DIM 128

#define SCAN_BLK 256
#define N_SCAN_BLOCKS ((N_NODES + SCAN_BLK - 1) / SCAN_BLK)   // 196
#define N_TILES ((N_NODES + 127) / 128)                        // 391
#define M_PAD   (N_TILES * 128)                                // 50048

// GEMM staging: one stage = 4 arrays x 128 rows x 40 bf16 (pitch 80B)
#define STAGE_ELEMS (128 * 40)
#define SMEM_DYN    (2 * 4 * STAGE_ELEMS * 2)                  // 81920 B

// ---------------- scratch (device globals: no allocs allowed) ----------------
__device__ int   g_is64;
__device__ int   g_deg     [N_NODES];
__device__ int   g_blocksum[N_SCAN_BLOCKS];
__device__ int   g_rowstart[N_NODES + 1];
__device__ int   g_cursor  [N_NODES];
__device__ int   g_csr_src [N_EDGES];
__device__ float g_dinv    [N_NODES];
// split-bf16 operands (pad rows of g_a1_* stay zero; never written)
__device__ __nv_bfloat16 g_a1_hi[M_PAD * IN_DIM];
__device__ __nv_bfloat16 g_a1_lo[M_PAD * IN_DIM];
__device__ __nv_bfloat16 g_h1_hi[M_PAD * HID_DIM];
__device__ __nv_bfloat16 g_h1_lo[M_PAD * HID_DIM];
__device__ float g_h2s[M_PAD * OUT_DIM];
// W transposed [N][K] + bf16-split
__device__ __nv_bfloat16 g_w1t_hi[HID_DIM * IN_DIM];
__device__ __nv_bfloat16 g_w1t_lo[HID_DIM * IN_DIM];
__device__ __nv_bfloat16 g_w2t_hi[OUT_DIM * HID_DIM];
__device__ __nv_bfloat16 g_w2t_lo[OUT_DIM * HID_DIM];

// ---------------- helpers ----------------
__device__ __forceinline__ u32 smem_u32(const void* p) {
    u32 a;
    asm("{ .reg .u64 t; cvta.to.shared.u64 t, %1; cvt.u32.u64 %0, t; }" : "=r"(a) : "l"(p));
    return a;
}
__device__ __forceinline__ u32 pack_bf16x2(__nv_bfloat16 a, __nv_bfloat16 b) {
    u32 lo = (u32)__bfloat16_as_ushort(a);
    u32 hi = (u32)__bfloat16_as_ushort(b);
    return lo | (hi << 16);
}
__device__ __forceinline__ void split_f32(float v, __nv_bfloat16& hi, __nv_bfloat16& lo) {
    hi = __float2bfloat16(v);
    lo = __float2bfloat16(v - __bfloat162float(hi));
}
__device__ __forceinline__ void ldsm_x4(u32& r0, u32& r1, u32& r2, u32& r3, u32 addr) {
    asm volatile("ldmatrix.sync.aligned.m8n8.x4.shared.b16 {%0,%1,%2,%3}, [%4];"
                 : "=r"(r0), "=r"(r1), "=r"(r2), "=r"(r3) : "r"(addr));
}
__device__ __forceinline__ void mma_bf16(float& d0, float& d1, float& d2, float& d3,
                                         u32 a0, u32 a1, u32 a2, u32 a3, u32 b0, u32 b1) {
    asm volatile(
        "mma.sync.aligned.m16n8k16.row.col.f32.bf16.bf16.f32 "
        "{%0,%1,%2,%3}, {%4,%5,%6,%7}, {%8,%9}, {%0,%1,%2,%3};"
        : "+f"(d0), "+f"(d1), "+f"(d2), "+f"(d3)
        : "r"(a0), "r"(a1), "r"(a2), "r"(a3), "r"(b0), "r"(b1));
}
__device__ __forceinline__ void cp_async16(u32 saddr, const void* gptr) {
    asm volatile("cp.async.ca.shared.global [%0], [%1], 16;" :: "r"(saddr), "l"(gptr));
}
__device__ __forceinline__ void cp_commit() {
    asm volatile("cp.async.commit_group;" ::: "memory");
}
__device__ __forceinline__ void cp_wait1() {
    asm volatile("cp.async.wait_group 1;" ::: "memory");
}
__device__ __forceinline__ void cp_wait0() {
    asm volatile("cp.async.wait_group 0;" ::: "memory");
}
__device__ __forceinline__ void decode_edge(const int* __restrict__ ei, int e, int& s, int& d) {
    if (g_is64) {
        const long long* p = (const long long*)ei;
        s = (int)p[e];
        d = (int)p[N_EDGES + e];
    } else {
        s = ei[e];
        d = ei[N_EDGES + e];
    }
}

// ---------------- prep: detect dtype + zero deg + convert both W ----------------
__global__ void __launch_bounds__(256) prep_kernel(
    const int* __restrict__ ei_raw,
    const float* __restrict__ W1,
    const float* __restrict__ W2)
{
    int i = blockIdx.x * 256 + threadIdx.x;

    if (blockIdx.x == 0) {
        __shared__ int s_or;
        if (threadIdx.x == 0) s_or = 0;
        __syncthreads();
        int v = ei_raw[2 * (threadIdx.x * 2) + 1] | ei_raw[2 * (threadIdx.x * 2 + 1) + 1];
        if (v) atomicOr(&s_or, 1);
        __syncthreads();
        if (threadIdx.x == 0) g_is64 = (s_or == 0) ? 1 : 0;
    }

    if (i < N_NODES) g_deg[i] = 0;

    if (i < IN_DIM * HID_DIM) {
        int k = i / HID_DIM;
        int n = i % HID_DIM;
        __nv_bfloat16 hi, lo;
        split_f32(W1[i], hi, lo);
        g_w1t_hi[n * IN_DIM + k] = hi;
        g_w1t_lo[n * IN_DIM + k] = lo;
    }
    if (i < HID_DIM * OUT_DIM) {
        int k = i / OUT_DIM;
        int n = i % OUT_DIM;
        __nv_bfloat16 hi, lo;
        split_f32(W2[i], hi, lo);
        g_w2t_hi[n * HID_DIM + k] = hi;
        g_w2t_lo[n * HID_DIM + k] = lo;
    }
}

// ---------------- histogram of dst ----------------
__global__ void hist_kernel(const int* __restrict__ ei_raw) {
    int e = blockIdx.x * blockDim.x + threadIdx.x;
    if (e >= N_EDGES) return;
    int s, d;
    decode_edge(ei_raw, e, s, d);
    atomicAdd(&g_deg[d], 1);
}

// ---------------- per-block degree sums ----------------
__global__ void __launch_bounds__(SCAN_BLK) block_sum_kernel() {
    __shared__ int sh[SCAN_BLK / 32];
    int i = blockIdx.x * SCAN_BLK + threadIdx.x;
    int v = (i < N_NODES) ? g_deg[i] : 0;
    #pragma unroll
    for (int o = 16; o > 0; o >>= 1) v += __shfl_down_sync(0xffffffffu, v, o);
    if ((threadIdx.x & 31) == 0) sh[threadIdx.x >> 5] = v;
    __syncthreads();
    if (threadIdx.x < SCAN_BLK / 32) {
        int w = sh[threadIdx.x];
        #pragma unroll
        for (int o = SCAN_BLK / 64; o > 0; o >>= 1) w += __shfl_down_sync(0xffu, w, o);
        if (threadIdx.x == 0) g_blocksum[blockIdx.x] = w;
    }
}

// ---------------- offsets: self-computed base (no separate blocksum scan) ----------------
__global__ void __launch_bounds__(SCAN_BLK) write_offsets_kernel() {
    __shared__ int sh[SCAN_BLK];
    __shared__ int s_warp[SCAN_BLK / 32];
    __shared__ int s_base;
    int tid = threadIdx.x;
    int bid = blockIdx.x;

    // base = sum of g_blocksum[0..bid)
    {
        int partial = 0;
        for (int j = tid; j < bid; j += SCAN_BLK) partial += g_blocksum[j];
        #pragma unroll
        for (int o = 16; o > 0; o >>= 1) partial += __shfl_down_sync(0xffffffffu, partial, o);
        if ((tid & 31) == 0) s_warp[tid >> 5] = partial;
        __syncthreads();
        if (tid == 0) {
            int b = 0;
            #pragma unroll
            for (int w = 0; w < SCAN_BLK / 32; w++) b += s_warp[w];
            s_base = b;
        }
    }

    int i = bid * SCAN_BLK + tid;
    int d = (i < N_NODES) ? g_deg[i] : 0;
    sh[tid] = d;
    __syncthreads();
    for (int ofs = 1; ofs < SCAN_BLK; ofs <<= 1) {
        int u = (tid >= ofs) ? sh[tid - ofs] : 0;
        __syncthreads();
        sh[tid] += u;
        __syncthreads();
    }
    if (i < N_NODES) {
        int start = s_base + sh[tid] - d;
        g_rowstart[i] = start;
        g_cursor[i]   = start;
        g_dinv[i]     = rsqrtf((float)d + 1.0f);
    }
    if (bid == N_SCAN_BLOCKS - 1 && tid == SCAN_BLK - 1)
        g_rowstart[N_NODES] = s_base + sh[tid];
}

__global__ void fill_csr_kernel(const int* __restrict__ ei_raw) {
    int e = blockIdx.x * blockDim.x + threadIdx.x;
    if (e >= N_EDGES) return;
    int s, d;
    decode_edge(ei_raw, e, s, d);
    int pos = atomicAdd(&g_cursor[d], 1);
    g_csr_src[pos] = s;
}

// ---------------- aggX: split-bf16 out of dinv[d]*(sum dinv[s]*x[s] + dinv[d]*x[d]) ----------------
__global__ void __launch_bounds__(256) aggx_kernel(const float* __restrict__ X)
{
    int node = ((blockIdx.x * blockDim.x + threadIdx.x) >> 5);
    int lane = threadIdx.x & 31;
    if (node >= N_NODES) return;

    int beg = g_rowstart[node];
    int end = g_rowstart[node + 1];
    int c = lane * 4;

    float wd = g_dinv[node];
    float4 v = *(const float4*)(X + (size_t)node * IN_DIM + c);
    float4 a = make_float4(v.x * wd, v.y * wd, v.z * wd, v.w * wd);

    int e = beg;
    for (; e + 1 < end; e += 2) {
        int s0 = g_csr_src[e];
        int s1 = g_csr_src[e + 1];
        float w0 = g_dinv[s0];
        float w1 = g_dinv[s1];
        float4 v0 = *(const float4*)(X + (size_t)s0 * IN_DIM + c);
        float4 v1 = *(const float4*)(X + (size_t)s1 * IN_DIM + c);
        a.x = fmaf(v0.x, w0, fmaf(v1.x, w1, a.x));
        a.y = fmaf(v0.y, w0, fmaf(v1.y, w1, a.y));
        a.z = fmaf(v0.z, w0, fmaf(v1.z, w1, a.z));
        a.w = fmaf(v0.w, w0, fmaf(v1.w, w1, a.w));
    }
    if (e < end) {
        int s0 = g_csr_src[e];
        float w0 = g_dinv[s0];
        float4 v0 = *(const float4*)(X + (size_t)s0 * IN_DIM + c);
        a.x = fmaf(v0.x, w0, a.x);
        a.y = fmaf(v0.y, w0, a.y);
        a.z = fmaf(v0.z, w0, a.z);
        a.w = fmaf(v0.w, w0, a.w);
    }

    a.x *= wd; a.y *= wd; a.z *= wd; a.w *= wd;

    __nv_bfloat16 h0, l0, h1, l1, h2, l2, h3, l3;
    split_f32(a.x, h0, l0);
    split_f32(a.y, h1, l1);
    split_f32(a.z, h2, l2);
    split_f32(a.w, h3, l3);
    uint2 hv, lv;
    hv.x = pack_bf16x2(h0, h1); hv.y = pack_bf16x2(h2, h3);
    lv.x = pack_bf16x2(l0, l1); lv.y = pack_bf16x2(l2, l3);
    *(uint2*)(g_a1_hi + (size_t)node * IN_DIM + c) = hv;
    *(uint2*)(g_a1_lo + (size_t)node * IN_DIM + c) = lv;
}

// ---------------- mma.sync split-bf16 GEMM, cp.async double-buffered ----------------
// C[M,NDIM] = A[M,KDIM] @ Wt[NDIM,KDIM]^T  (3-term split accumulation)
// SPLIT_OUT: C' = relu(C + bias) split-> (Chi, Clo) bf16;  else: Cf = C * dinv[row]
template <int KDIM, int NDIM, bool SPLIT_OUT>
__device__ __forceinline__ void mma_gemm_body(
    const __nv_bfloat16* __restrict__ Ahi, const __nv_bfloat16* __restrict__ Alo,
    const __nv_bfloat16* __restrict__ Whi, const __nv_bfloat16* __restrict__ Wlo,
    const float* __restrict__ bias,
    __nv_bfloat16* __restrict__ Chi, __nv_bfloat16* __restrict__ Clo,
    float* __restrict__ Cf)
{
    extern __shared__ __nv_bfloat16 smem_dyn[];
    // layout: [stage][array] arrays: 0=Ah 1=Al 2=Bh 3=Bl ; each 128x40 bf16
    const int tid    = threadIdx.x;      // 256 threads
    const int lane   = tid & 31;
    const int warp   = tid >> 5;
    const int warp_m = warp & 3;
    const int warp_n = warp >> 2;
    const int bm     = blockIdx.x * 128;
    const int bn     = blockIdx.y * 128;

    float acc[2][8][4];
    #pragma unroll
    for (int i = 0; i < 2; i++)
        #pragma unroll
        for (int j = 0; j < 8; j++)
            #pragma unroll
            for (int q = 0; q < 4; q++) acc[i][j][q] = 0.f;

    u32 sbase[2][4];
    #pragma unroll
    for (int st = 0; st < 2; st++)
        #pragma unroll
        for (int ar = 0; ar < 4; ar++)
            sbase[st][ar] = smem_u32(smem_dyn + (st * 4 + ar) * STAGE_ELEMS);

    // per-thread staging coords (2 slots of 16B per array)
    const int row0 = tid >> 2;
    const int c40  = (tid & 3) * 8;      // bf16 index within 32-chunk

    // frag address components
    const int a_lr = lane & 15;
    const int a_ko = (lane < 16) ? 0 : 8;
    const int b_l8 = lane & 7;
    const int b_gr = lane >> 3;
    const int b_nrow = (b_gr & 2) ? (b_l8 + 8) : b_l8;
    const int b_ko   = (b_gr & 1) ? 8 : 0;

    const int KC = KDIM / 32;

    // stage loader: chunk kc into stage st
    auto stage_load = [&](int st, int kc) {
        #pragma unroll
        for (int l = 0; l < 2; l++) {
            int row = row0 + l * 64;
            size_t ga = (size_t)(bm + row) * KDIM + kc * 32 + c40;
            size_t gb = (size_t)(bn + row) * KDIM + kc * 32 + c40;
            u32 so = (u32)(row * 40 + c40) * 2;
            cp_async16(sbase[st][0] + so, Ahi + ga);
            cp_async16(sbase[st][1] + so, Alo + ga);
            cp_async16(sbase[st][2] + so, Whi + gb);
            cp_async16(sbase[st][3] + so, Wlo + gb);
        }
        cp_commit();
    };

    stage_load(0, 0);

    for (int kc = 0; kc < KC; kc++) {
        int st = kc & 1;
        if (kc + 1 < KC) {
            stage_load(st ^ 1, kc + 1);
            cp_wait1();
        } else {
            cp_wait0();
        }
        __syncthreads();

        const u32 sAh_b = sbase[st][0];
        const u32 sAl_b = sbase[st][1];
        const u32 sBh_b = sbase[st][2];
        const u32 sBl_b = sbase[st][3];

        #pragma unroll
        for (int ks = 0; ks < 32; ks += 16) {
            u32 ah[2][4], al[2][4];
            #pragma unroll
            for (int mt = 0; mt < 2; mt++) {
                u32 off = (u32)((warp_m * 32 + mt * 16 + a_lr) * 40 + ks + a_ko) * 2;
                ldsm_x4(ah[mt][0], ah[mt][1], ah[mt][2], ah[mt][3], sAh_b + off);
                ldsm_x4(al[mt][0], al[mt][1], al[mt][2], al[mt][3], sAl_b + off);
            }
            u32 bh[8][2], bl[8][2];
            #pragma unroll
            for (int ntp = 0; ntp < 4; ntp++) {
                u32 off = (u32)((warp_n * 64 + ntp * 16 + b_nrow) * 40 + ks + b_ko) * 2;
                ldsm_x4(bh[2 * ntp][0], bh[2 * ntp][1], bh[2 * ntp + 1][0], bh[2 * ntp + 1][1], sBh_b + off);
                ldsm_x4(bl[2 * ntp][0], bl[2 * ntp][1], bl[2 * ntp + 1][0], bl[2 * ntp + 1][1], sBl_b + off);
            }
            #pragma unroll
            for (int mt = 0; mt < 2; mt++) {
                #pragma unroll
                for (int nt = 0; nt < 8; nt++) {
                    float* d = acc[mt][nt];
                    mma_bf16(d[0], d[1], d[2], d[3],
                             ah[mt][0], ah[mt][1], ah[mt][2], ah[mt][3],
                             bh[nt][0], bh[nt][1]);
                    mma_bf16(d[0], d[1], d[2], d[3],
                             ah[mt][0], ah[mt][1], ah[mt][2], ah[mt][3],
                             bl[nt][0], bl[nt][1]);
                    mma_bf16(d[0], d[1], d[2], d[3],
                             al[mt][0], al[mt][1], al[mt][2], al[mt][3],
                             bh[nt][0], bh[nt][1]);
                }
            }
        }
        __syncthreads();
    }

    // ---- epilogue ----
    const int g   = lane >> 2;
    const int tig = lane & 3;
    #pragma unroll
    for (int mt = 0; mt < 2; mt++) {
        int r0 = bm + warp_m * 32 + mt * 16 + g;
        int r1 = r0 + 8;
        #pragma unroll
        for (int nt = 0; nt < 8; nt++) {
            int col = bn + warp_n * 64 + nt * 8 + tig * 2;
            float c0 = acc[mt][nt][0];
            float c1 = acc[mt][nt][1];
            float c2 = acc[mt][nt][2];
            float c3 = acc[mt][nt][3];
            if (SPLIT_OUT) {
                float bb0 = bias[col];
                float bb1 = bias[col + 1];
                float v0 = fmaxf(c0 + bb0, 0.f);
                float v1 = fmaxf(c1 + bb1, 0.f);
                float v2 = fmaxf(c2 + bb0, 0.f);
                float v3 = fmaxf(c3 + bb1, 0.f);
                __nv_bfloat16 h0, l0, h1, l1;
                split_f32(v0, h0, l0);
                split_f32(v1, h1, l1);
                *(u32*)(Chi + (size_t)r0 * NDIM + col) = pack_bf16x2(h0, h1);
                *(u32*)(Clo + (size_t)r0 * NDIM + col) = pack_bf16x2(l0, l1);
                split_f32(v2, h0, l0);
                split_f32(v3, h1, l1);
                *(u32*)(Chi + (size_t)r1 * NDIM + col) = pack_bf16x2(h0, h1);
                *(u32*)(Clo + (size_t)r1 * NDIM + col) = pack_bf16x2(l0, l1);
            } else {
                float s0 = (r0 < N_NODES) ? g_dinv[r0] : 0.f;
                float s1 = (r1 < N_NODES) ? g_dinv[r1] : 0.f;
                float2 o0 = make_float2(c0 * s0, c1 * s0);
                float2 o1 = make_float2(c2 * s1, c3 * s1);
                *(float2*)(Cf + (size_t)r0 * NDIM + col) = o0;
                *(float2*)(Cf + (size_t)r1 * NDIM + col) = o1;
            }
        }
    }
}

__global__ void __launch_bounds__(256) mma_gemm1_kernel(const float* __restrict__ b1)
{
    mma_gemm_body<IN_DIM, HID_DIM, true>(g_a1_hi, g_a1_lo, g_w1t_hi, g_w1t_lo,
                                         b1, g_h1_hi, g_h1_lo, (float*)0);
}

__global__ void __launch_bounds__(256) mma_gemm2_kernel()
{
    mma_gemm_body<HID_DIM, OUT_DIM, false>(g_h1_hi, g_h1_lo, g_w2t_hi, g_w2t_lo,
                                           (const float*)0, (__nv_bfloat16*)0, (__nv_bfloat16*)0, g_h2s);
}

// ---------------- agg2: out[d] = dinv[d]*(sum h2s[src] + h2s[d]) + b2 ----------------
__global__ void __launch_bounds__(256) agg2_kernel(
    const float* __restrict__ b2,
    float* __restrict__ out)
{
    int node = ((blockIdx.x * blockDim.x + threadIdx.x) >> 5);
    int lane = threadIdx.x & 31;
    if (node >= N_NODES) return;

    int beg = g_rowstart[node];
    int end = g_rowstart[node + 1];
    int c0 = lane * 4;

    float4 a0 = *(const float4*)(g_h2s + (size_t)node * OUT_DIM + c0);

    int e = beg;
    for (; e + 1 < end; e += 2) {
        int s0 = g_csr_src[e];
        int s1 = g_csr_src[e + 1];
        float4 v0 = *(const float4*)(g_h2s + (size_t)s0 * OUT_DIM + c0);
        float4 v1 = *(const float4*)(g_h2s + (size_t)s1 * OUT_DIM + c0);
        a0.x += v0.x + v1.x; a0.y += v0.y + v1.y;
        a0.z += v0.z + v1.z; a0.w += v0.w + v1.w;
    }
    if (e < end) {
        int s0 = g_csr_src[e];
        float4 v0 = *(const float4*)(g_h2s + (size_t)s0 * OUT_DIM + c0);
        a0.x += v0.x; a0.y += v0.y; a0.z += v0.z; a0.w += v0.w;
    }

    float w = g_dinv[node];
    float4 bb = *(const float4*)(b2 + c0);
    a0.x = a0.x * w + bb.x;
    a0.y = a0.y * w + bb.y;
    a0.z = a0.z * w + bb.z;
    a0.w = a0.w * w + bb.w;
    *(float4*)(out + (size_t)node * OUT_DIM + c0) = a0;
}

// ---------------- launch ----------------
extern "C" void kernel_launch(void* const* d_in, const int* in_sizes, int n_in,
                              void* d_out, int out_size)
{
    const float* x  = (const float*)d_in[0];
    const int*   ei = (const int*)d_in[1];
    const float* W1 = (const float*)d_in[2];
    const float* b1 = (const float*)d_in[3];
    const float* W2 = (const float*)d_in[4];
    const float* b2 = (const float*)d_in[5];
    float* out = (float*)d_out;

    cudaFuncSetAttribute(mma_gemm1_kernel, cudaFuncAttributeMaxDynamicSharedMemorySize, SMEM_DYN);
    cudaFuncSetAttribute(mma_gemm2_kernel, cudaFuncAttributeMaxDynamicSharedMemorySize, SMEM_DYN);

    // preprocessing: detect + zero deg + convert W (one kernel), then CSR build
    prep_kernel<<<N_SCAN_BLOCKS, 256>>>(ei, W1, W2);
    hist_kernel<<<(N_EDGES + 255) / 256, 256>>>(ei);
    block_sum_kernel<<<N_SCAN_BLOCKS, SCAN_BLK>>>();
    write_offsets_kernel<<<N_SCAN_BLOCKS, SCAN_BLK>>>();
    fill_csr_kernel<<<(N_EDGES + 255) / 256, 256>>>(ei);

    // layer 1: aggregate (split-bf16 out) then HMMA GEMM (fused relu+b1, split-bf16 out)
    aggx_kernel<<<(N_NODES + 7) / 8, 256>>>(x);
    {
        dim3 grid(N_TILES, HID_DIM / 128);
        mma_gemm1_kernel<<<grid, 256, SMEM_DYN>>>(b1);
    }

    // layer 2: HMMA GEMM (*dinv epilogue) then aggregate
    {
        dim3 grid(N_TILES, OUT_DIM / 128);
        mma_gemm2_kernel<<<grid, 256, SMEM_DYN>>>();
    }
    agg2_kernel<<<(N_NODES + 7) / 8, 256>>>(b2, out);
}